// round 12
// baseline (speedup 1.0000x reference)
#include <cuda_runtime.h>
#include <cuda_fp16.h>
#include <cstdint>

#define N_USERS 30000
#define N_NODES 100000
#define N_EDGES 1600000

#define SCAN_BS 512
#define SCAN_NB ((N_NODES + SCAN_BS - 1) / SCAN_BS)   // 196
#define EDGE_CAP 1536                                 // smem edge buffer per block

typedef unsigned long long ull;

// Scratch
__device__ float4  g_egoA[N_NODES * 16];     // layer-0 ego fp32
__device__ float2  g_egoB[N_NODES * 32];     // layer-1 ego fp32
__device__ __half2 g_egoAh[N_NODES * 32];    // fp16 shadows (gather only)
__device__ __half2 g_egoBh[N_NODES * 32];
__device__ int  g_cnt[N_NODES];
__device__ int  g_off[N_NODES + 1];
__device__ int  g_cur[N_NODES];
__device__ ull  g_state[SCAN_NB];
__device__ int2 g_edges[N_EDGES];            // row-sorted (col, half2(v,v) bits)

__device__ __forceinline__ __half2 h2bits(int b) {
    __half2 h; *(int*)&h = b; return h;
}
__device__ __forceinline__ uint32_t smem_u32(const void* p) {
    return (uint32_t)__cvta_generic_to_shared(p);
}

#define LDSM_X4(r0, r1, r2, r3, addr) \
    asm volatile("ldmatrix.sync.aligned.m8n8.x4.shared.b16 {%0,%1,%2,%3}, [%4];" \
        : "=r"(r0), "=r"(r1), "=r"(r2), "=r"(r3) : "r"(addr))
#define LDSM_X2T(r0, r1, addr) \
    asm volatile("ldmatrix.sync.aligned.m8n8.x2.trans.shared.b16 {%0,%1}, [%2];" \
        : "=r"(r0), "=r"(r1) : "r"(addr))
#define MMA16816(d, a0, a1, a2, a3, b0, b1) \
    asm volatile("mma.sync.aligned.m16n8k16.row.col.f32.f16.f16.f32 " \
        "{%0,%1,%2,%3},{%4,%5,%6,%7},{%8,%9},{%0,%1,%2,%3};" \
        : "+f"((d)[0]), "+f"((d)[1]), "+f"((d)[2]), "+f"((d)[3]) \
        : "r"(a0), "r"(a1), "r"(a2), "r"(a3), "r"(b0), "r"(b1))

// ---------------------------------------------------------------------------
// k_init: ego0 (fp32 + fp16 shadow), out[:,0:64], edge histogram.
// ---------------------------------------------------------------------------
__global__ __launch_bounds__(256) void k_init(
    const float4* __restrict__ user4,
    const float4* __restrict__ ent4,
    const int* __restrict__ rows,
    float4* __restrict__ out4)
{
    int idx = blockIdx.x * blockDim.x + threadIdx.x;
    if (idx < N_EDGES) atomicAdd(&g_cnt[rows[idx]], 1);
    if (idx >= N_NODES * 16) return;
    int row = idx >> 4;
    int part = idx & 15;
    float4 v = (row < N_USERS) ? user4[row * 16 + part]
                               : ent4[(row - N_USERS) * 16 + part];
    g_egoA[idx] = v;
    g_egoAh[row * 32 + 2 * part]     = __floats2half2_rn(v.x, v.y);
    g_egoAh[row * 32 + 2 * part + 1] = __floats2half2_rn(v.z, v.w);
    out4[row * 40 + part] = v;
}

// ---------------------------------------------------------------------------
// Single-pass exclusive scan (decoupled lookback).
// ---------------------------------------------------------------------------
__global__ __launch_bounds__(SCAN_BS) void k_scan()
{
    __shared__ int warp_sums[16];
    __shared__ int blk_prefix;

    int tid = threadIdx.x;
    int bid = blockIdx.x;
    int lane = tid & 31;
    int wid = tid >> 5;
    int i = bid * SCAN_BS + tid;
    int v = (i < N_NODES) ? g_cnt[i] : 0;

    int x = v;
    #pragma unroll
    for (int off = 1; off < 32; off <<= 1) {
        int t = __shfl_up_sync(0xFFFFFFFFu, x, off);
        if (lane >= off) x += t;
    }
    if (lane == 31) warp_sums[wid] = x;
    __syncthreads();
    if (wid == 0) {
        int s = (lane < 16) ? warp_sums[lane] : 0;
        #pragma unroll
        for (int off = 1; off < 16; off <<= 1) {
            int t = __shfl_up_sync(0xFFFFFFFFu, s, off);
            if (lane >= off) s += t;
        }
        if (lane < 16) warp_sums[lane] = s;
    }
    __syncthreads();
    int incl = x + (wid > 0 ? warp_sums[wid - 1] : 0);
    int block_total = warp_sums[15];

    if (tid == 0) {
        if (bid == 0) {
            atomicExch(&g_state[0], (2ULL << 32) | (unsigned)block_total);
            blk_prefix = 0;
        } else {
            atomicExch(&g_state[bid], (1ULL << 32) | (unsigned)block_total);
            int pref = 0;
            int j = bid - 1;
            while (true) {
                ull s = atomicAdd(&g_state[j], 0ULL);
                unsigned st = (unsigned)(s >> 32);
                if (st == 2) { pref += (int)(unsigned)s; break; }
                if (st == 1) { pref += (int)(unsigned)s; j--; }
            }
            atomicExch(&g_state[bid], (2ULL << 32) | (unsigned)(pref + block_total));
            blk_prefix = pref;
        }
    }
    __syncthreads();

    int excl = blk_prefix + incl - v;
    if (i < N_NODES) { g_off[i] = excl; g_cur[i] = excl; }
    if (i == N_NODES - 1) g_off[N_NODES] = N_EDGES;
}

__global__ __launch_bounds__(256) void k_scatter(
    const int* __restrict__ rows,
    const int* __restrict__ cols,
    const float* __restrict__ vals)
{
    int e = blockIdx.x * blockDim.x + threadIdx.x;
    if (e >= N_EDGES) return;
    int pos = atomicAdd(&g_cur[rows[e]], 1);
    float v = vals[e];
    __half2 vv = __floats2half2_rn(v, v);
    g_edges[pos] = make_int2(cols[e], *(const int*)&vv);
}

// ---------------------------------------------------------------------------
// Gather from GLOBAL descriptors (fallback path).
// ---------------------------------------------------------------------------
__device__ __forceinline__ void gather_row_g(
    const __half2* __restrict__ egoH, int lane, int s, int e,
    float& ax, float& ay)
{
    int i = s;
    if ((i & 1) && i < e) {
        int2 cv = g_edges[i];
        __half2 p = __hmul2(h2bits(cv.y), egoH[cv.x * 32 + lane]);
        float2 f = __half22float2(p);
        ax += f.x; ay += f.y;
        i++;
    }
    const int4* ep = (const int4*)g_edges;
    for (; i + 7 < e; i += 8) {
        int4 p0 = ep[(i >> 1) + 0];
        int4 p1 = ep[(i >> 1) + 1];
        int4 p2 = ep[(i >> 1) + 2];
        int4 p3 = ep[(i >> 1) + 3];
        __half2 x0 = egoH[p0.x * 32 + lane];
        __half2 x1 = egoH[p0.z * 32 + lane];
        __half2 x2 = egoH[p1.x * 32 + lane];
        __half2 x3 = egoH[p1.z * 32 + lane];
        __half2 x4 = egoH[p2.x * 32 + lane];
        __half2 x5 = egoH[p2.z * 32 + lane];
        __half2 x6 = egoH[p3.x * 32 + lane];
        __half2 x7 = egoH[p3.z * 32 + lane];
        __half2 acc = __hmul2(h2bits(p0.y), x0);
        acc = __hfma2(h2bits(p0.w), x1, acc);
        acc = __hfma2(h2bits(p1.y), x2, acc);
        acc = __hfma2(h2bits(p1.w), x3, acc);
        acc = __hfma2(h2bits(p2.y), x4, acc);
        acc = __hfma2(h2bits(p2.w), x5, acc);
        acc = __hfma2(h2bits(p3.y), x6, acc);
        acc = __hfma2(h2bits(p3.w), x7, acc);
        float2 f = __half22float2(acc);
        ax += f.x; ay += f.y;
    }
    for (; i < e; i++) {
        int2 cv = g_edges[i];
        __half2 p = __hmul2(h2bits(cv.y), egoH[cv.x * 32 + lane]);
        float2 f = __half22float2(p);
        ax += f.x; ay += f.y;
    }
}

// ---------------------------------------------------------------------------
// Gather from SMEM descriptors (s, e relative to block's edge window).
// ---------------------------------------------------------------------------
__device__ __forceinline__ void gather_row_s(
    const int2* __restrict__ sE,
    const __half2* __restrict__ egoH, int lane, int s, int e,
    float& ax, float& ay)
{
    int i = s;
    if ((i & 1) && i < e) {
        int2 cv = sE[i];
        __half2 p = __hmul2(h2bits(cv.y), egoH[cv.x * 32 + lane]);
        float2 f = __half22float2(p);
        ax += f.x; ay += f.y;
        i++;
    }
    const int4* ep = (const int4*)sE;
    for (; i + 7 < e; i += 8) {
        int4 p0 = ep[(i >> 1) + 0];
        int4 p1 = ep[(i >> 1) + 1];
        int4 p2 = ep[(i >> 1) + 2];
        int4 p3 = ep[(i >> 1) + 3];
        __half2 x0 = egoH[p0.x * 32 + lane];
        __half2 x1 = egoH[p0.z * 32 + lane];
        __half2 x2 = egoH[p1.x * 32 + lane];
        __half2 x3 = egoH[p1.z * 32 + lane];
        __half2 x4 = egoH[p2.x * 32 + lane];
        __half2 x5 = egoH[p2.z * 32 + lane];
        __half2 x6 = egoH[p3.x * 32 + lane];
        __half2 x7 = egoH[p3.z * 32 + lane];
        __half2 acc = __hmul2(h2bits(p0.y), x0);
        acc = __hfma2(h2bits(p0.w), x1, acc);
        acc = __hfma2(h2bits(p1.y), x2, acc);
        acc = __hfma2(h2bits(p1.w), x3, acc);
        acc = __hfma2(h2bits(p2.y), x4, acc);
        acc = __hfma2(h2bits(p2.w), x5, acc);
        acc = __hfma2(h2bits(p3.y), x6, acc);
        acc = __hfma2(h2bits(p3.w), x7, acc);
        float2 f = __half22float2(acc);
        ax += f.x; ay += f.y;
    }
    for (; i < e; i++) {
        int2 cv = sE[i];
        __half2 p = __hmul2(h2bits(cv.y), egoH[cv.x * 32 + lane]);
        float2 f = __half22float2(p);
        ax += f.x; ay += f.y;
    }
}

// ---------------------------------------------------------------------------
// Fused layer 1: edge stage -> gather (8 rows/warp) -> fp16 am tiles ->
// mma.sync GEMMs -> lrelu/sum/l2norm. Block = 64 rows.
// ---------------------------------------------------------------------------
__global__ __launch_bounds__(256) void k_layer1(
    const float* __restrict__ W1, const float* __restrict__ b1,
    const float* __restrict__ W2, const float* __restrict__ b2,
    float* __restrict__ out)
{
    __shared__ __align__(16) __half sA[64 * 72];   // a = ego + side
    __shared__ __align__(16) __half sM[64 * 72];   // m = ego * side
    __shared__ __align__(16) __half sW1[64 * 72];
    __shared__ __align__(16) __half sW2[64 * 72];
    __shared__ __align__(16) int2 sE[EDGE_CAP];
    __shared__ float sP[64][2];

    int tid = threadIdx.x;
    int wid = tid >> 5;
    int lane = tid & 31;
    int rbase = blockIdx.x * 64;
    int rend = min(rbase + 64, N_NODES);

    // weights -> fp16 smem (padded stride 72)
    for (int i = tid; i < 4096; i += 256) {
        int k = i >> 6, n = i & 63;
        sW1[k * 72 + n] = __float2half(W1[i]);
        sW2[k * 72 + n] = __float2half(W2[i]);
    }
    if (rbase + 64 > N_NODES) {
        for (int i = tid; i < 64 * 36; i += 256) {
            ((uint32_t*)sA)[i] = 0;
            ((uint32_t*)sM)[i] = 0;
        }
    }
    // stage this block's edge window (contiguous, coalesced)
    int ebase = g_off[rbase];
    int etotal = g_off[rend] - ebase;
    bool use_smem = (etotal <= EDGE_CAP);
    if (use_smem) {
        for (int i = tid; i < etotal; i += 256)
            sE[i] = g_edges[ebase + i];
    }
    __syncthreads();

    // gather phase: warp handles rows [wid*8, wid*8+8)
    const float2* egoA2 = (const float2*)g_egoA;
    for (int rr = 0; rr < 8; rr++) {
        int lrow = wid * 8 + rr;
        int r = rbase + lrow;
        if (r < N_NODES) {
            int s = g_off[r], e = g_off[r + 1];
            float ax = 0.f, ay = 0.f;
            if (use_smem) gather_row_s(sE, g_egoAh, lane, s - ebase, e - ebase, ax, ay);
            else          gather_row_g(g_egoAh, lane, s, e, ax, ay);
            float2 eg = egoA2[r * 32 + lane];
            *(__half2*)&sA[lrow * 72 + 2 * lane] = __floats2half2_rn(eg.x + ax, eg.y + ay);
            *(__half2*)&sM[lrow * 72 + 2 * lane] = __floats2half2_rn(eg.x * ax, eg.y * ay);
        }
    }
    __syncthreads();

    // mma phase
    int t = wid >> 1;
    int h = wid & 1;

    float d1[16], d2[16];
    #pragma unroll
    for (int nt = 0; nt < 4; nt++) {
        int c = h * 32 + nt * 8 + (lane & 3) * 2;
        float bb1a = b1[c], bb1b = b1[c + 1];
        float bb2a = b2[c], bb2b = b2[c + 1];
        d1[nt * 4 + 0] = bb1a; d1[nt * 4 + 1] = bb1b;
        d1[nt * 4 + 2] = bb1a; d1[nt * 4 + 3] = bb1b;
        d2[nt * 4 + 0] = bb2a; d2[nt * 4 + 1] = bb2b;
        d2[nt * 4 + 2] = bb2a; d2[nt * 4 + 3] = bb2b;
    }

    int q = lane >> 3;
    int ri = lane & 7;
    int arow = t * 16 + (q & 1) * 8 + ri;
    int acol = (q >> 1) * 8;
    uint32_t aA = smem_u32(&sA[arow * 72 + acol]);
    uint32_t aM = smem_u32(&sM[arow * 72 + acol]);
    int g2 = q & 1;
    uint32_t bW1 = smem_u32(&sW1[(g2 * 8 + ri) * 72 + h * 32]);
    uint32_t bW2 = smem_u32(&sW2[(g2 * 8 + ri) * 72 + h * 32]);

    #pragma unroll
    for (int ks = 0; ks < 4; ks++) {
        uint32_t a0, a1, a2, a3;
        LDSM_X4(a0, a1, a2, a3, aA + ks * 32);
        #pragma unroll
        for (int nt = 0; nt < 4; nt++) {
            uint32_t b0, b1r;
            LDSM_X2T(b0, b1r, bW1 + ks * 16 * 144 + nt * 16);
            MMA16816(&d1[nt * 4], a0, a1, a2, a3, b0, b1r);
        }
        LDSM_X4(a0, a1, a2, a3, aM + ks * 32);
        #pragma unroll
        for (int nt = 0; nt < 4; nt++) {
            uint32_t b0, b1r;
            LDSM_X2T(b0, b1r, bW2 + ks * 16 * 144 + nt * 16);
            MMA16816(&d2[nt * 4], a0, a1, a2, a3, b0, b1r);
        }
    }

    // epilogue
    float ss0 = 0.f, ss1 = 0.f;
    #pragma unroll
    for (int nt = 0; nt < 4; nt++) {
        #pragma unroll
        for (int i = 0; i < 4; i++) {
            float v1 = d1[nt * 4 + i], v2 = d2[nt * 4 + i];
            float v = (v1 > 0.f ? v1 : 0.01f * v1) + (v2 > 0.f ? v2 : 0.01f * v2);
            d1[nt * 4 + i] = v;
            if (i < 2) ss0 += v * v; else ss1 += v * v;
        }
    }
    ss0 += __shfl_xor_sync(0xFFFFFFFFu, ss0, 1);
    ss0 += __shfl_xor_sync(0xFFFFFFFFu, ss0, 2);
    ss1 += __shfl_xor_sync(0xFFFFFFFFu, ss1, 1);
    ss1 += __shfl_xor_sync(0xFFFFFFFFu, ss1, 2);
    if ((lane & 3) == 0) {
        sP[t * 16 + (lane >> 2)][h] = ss0;
        sP[t * 16 + (lane >> 2) + 8][h] = ss1;
    }
    __syncthreads();

    int r0 = t * 16 + (lane >> 2);
    int r1 = r0 + 8;
    float inv0 = 1.f / fmaxf(sqrtf(sP[r0][0] + sP[r0][1]), 1e-12f);
    float inv1 = 1.f / fmaxf(sqrtf(sP[r1][0] + sP[r1][1]), 1e-12f);
    int gr0 = rbase + r0, gr1 = rbase + r1;
    #pragma unroll
    for (int nt = 0; nt < 4; nt++) {
        int c = h * 32 + nt * 8 + (lane & 3) * 2;
        if (gr0 < N_NODES) {
            float x0 = d1[nt * 4 + 0] * inv0, x1 = d1[nt * 4 + 1] * inv0;
            *(float2*)&out[gr0 * 160 + 64 + c] = make_float2(x0, x1);
            g_egoB[gr0 * 32 + (c >> 1)] = make_float2(x0, x1);
            g_egoBh[gr0 * 32 + (c >> 1)] = __floats2half2_rn(x0, x1);
        }
        if (gr1 < N_NODES) {
            float x0 = d1[nt * 4 + 2] * inv1, x1 = d1[nt * 4 + 3] * inv1;
            *(float2*)&out[gr1 * 160 + 64 + c] = make_float2(x0, x1);
            g_egoB[gr1 * 32 + (c >> 1)] = make_float2(x0, x1);
            g_egoBh[gr1 * 32 + (c >> 1)] = __floats2half2_rn(x0, x1);
        }
    }
}

// ---------------------------------------------------------------------------
// Fused layer 2: same structure, N=32.
// ---------------------------------------------------------------------------
__global__ __launch_bounds__(256) void k_layer2(
    const float* __restrict__ W1, const float* __restrict__ b1,
    const float* __restrict__ W2, const float* __restrict__ b2,
    float* __restrict__ out)
{
    __shared__ __align__(16) __half sA[64 * 72];
    __shared__ __align__(16) __half sM[64 * 72];
    __shared__ __align__(16) __half sW1[64 * 40];
    __shared__ __align__(16) __half sW2[64 * 40];
    __shared__ __align__(16) int2 sE[EDGE_CAP];
    __shared__ float sP[64][2];

    int tid = threadIdx.x;
    int wid = tid >> 5;
    int lane = tid & 31;
    int rbase = blockIdx.x * 64;
    int rend = min(rbase + 64, N_NODES);

    for (int i = tid; i < 2048; i += 256) {
        int k = i >> 5, n = i & 31;
        sW1[k * 40 + n] = __float2half(W1[i]);
        sW2[k * 40 + n] = __float2half(W2[i]);
    }
    if (rbase + 64 > N_NODES) {
        for (int i = tid; i < 64 * 36; i += 256) {
            ((uint32_t*)sA)[i] = 0;
            ((uint32_t*)sM)[i] = 0;
        }
    }
    int ebase = g_off[rbase];
    int etotal = g_off[rend] - ebase;
    bool use_smem = (etotal <= EDGE_CAP);
    if (use_smem) {
        for (int i = tid; i < etotal; i += 256)
            sE[i] = g_edges[ebase + i];
    }
    __syncthreads();

    for (int rr = 0; rr < 8; rr++) {
        int lrow = wid * 8 + rr;
        int r = rbase + lrow;
        if (r < N_NODES) {
            int s = g_off[r], e = g_off[r + 1];
            float ax = 0.f, ay = 0.f;
            if (use_smem) gather_row_s(sE, g_egoBh, lane, s - ebase, e - ebase, ax, ay);
            else          gather_row_g(g_egoBh, lane, s, e, ax, ay);
            float2 eg = g_egoB[r * 32 + lane];
            *(__half2*)&sA[lrow * 72 + 2 * lane] = __floats2half2_rn(eg.x + ax, eg.y + ay);
            *(__half2*)&sM[lrow * 72 + 2 * lane] = __floats2half2_rn(eg.x * ax, eg.y * ay);
        }
    }
    __syncthreads();

    int t = wid >> 1;
    int h = wid & 1;

    float d1[8], d2[8];
    #pragma unroll
    for (int nt = 0; nt < 2; nt++) {
        int c = h * 16 + nt * 8 + (lane & 3) * 2;
        float bb1a = b1[c], bb1b = b1[c + 1];
        float bb2a = b2[c], bb2b = b2[c + 1];
        d1[nt * 4 + 0] = bb1a; d1[nt * 4 + 1] = bb1b;
        d1[nt * 4 + 2] = bb1a; d1[nt * 4 + 3] = bb1b;
        d2[nt * 4 + 0] = bb2a; d2[nt * 4 + 1] = bb2b;
        d2[nt * 4 + 2] = bb2a; d2[nt * 4 + 3] = bb2b;
    }

    int q = lane >> 3;
    int ri = lane & 7;
    int arow = t * 16 + (q & 1) * 8 + ri;
    int acol = (q >> 1) * 8;
    uint32_t aA = smem_u32(&sA[arow * 72 + acol]);
    uint32_t aM = smem_u32(&sM[arow * 72 + acol]);
    int g2 = q & 1;
    uint32_t bW1 = smem_u32(&sW1[(g2 * 8 + ri) * 40 + h * 16]);
    uint32_t bW2 = smem_u32(&sW2[(g2 * 8 + ri) * 40 + h * 16]);

    #pragma unroll
    for (int ks = 0; ks < 4; ks++) {
        uint32_t a0, a1, a2, a3;
        LDSM_X4(a0, a1, a2, a3, aA + ks * 32);
        #pragma unroll
        for (int nt = 0; nt < 2; nt++) {
            uint32_t b0, b1r;
            LDSM_X2T(b0, b1r, bW1 + ks * 16 * 80 + nt * 16);
            MMA16816(&d1[nt * 4], a0, a1, a2, a3, b0, b1r);
        }
        LDSM_X4(a0, a1, a2, a3, aM + ks * 32);
        #pragma unroll
        for (int nt = 0; nt < 2; nt++) {
            uint32_t b0, b1r;
            LDSM_X2T(b0, b1r, bW2 + ks * 16 * 80 + nt * 16);
            MMA16816(&d2[nt * 4], a0, a1, a2, a3, b0, b1r);
        }
    }

    float ss0 = 0.f, ss1 = 0.f;
    #pragma unroll
    for (int nt = 0; nt < 2; nt++) {
        #pragma unroll
        for (int i = 0; i < 4; i++) {
            float v1 = d1[nt * 4 + i], v2 = d2[nt * 4 + i];
            float v = (v1 > 0.f ? v1 : 0.01f * v1) + (v2 > 0.f ? v2 : 0.01f * v2);
            d1[nt * 4 + i] = v;
            if (i < 2) ss0 += v * v; else ss1 += v * v;
        }
    }
    ss0 += __shfl_xor_sync(0xFFFFFFFFu, ss0, 1);
    ss0 += __shfl_xor_sync(0xFFFFFFFFu, ss0, 2);
    ss1 += __shfl_xor_sync(0xFFFFFFFFu, ss1, 1);
    ss1 += __shfl_xor_sync(0xFFFFFFFFu, ss1, 2);
    if ((lane & 3) == 0) {
        sP[t * 16 + (lane >> 2)][h] = ss0;
        sP[t * 16 + (lane >> 2) + 8][h] = ss1;
    }
    __syncthreads();

    int r0 = t * 16 + (lane >> 2);
    int r1 = r0 + 8;
    float inv0 = 1.f / fmaxf(sqrtf(sP[r0][0] + sP[r0][1]), 1e-12f);
    float inv1 = 1.f / fmaxf(sqrtf(sP[r1][0] + sP[r1][1]), 1e-12f);
    int gr0 = rbase + r0, gr1 = rbase + r1;
    #pragma unroll
    for (int nt = 0; nt < 2; nt++) {
        int c = h * 16 + nt * 8 + (lane & 3) * 2;
        if (gr0 < N_NODES) {
            *(float2*)&out[gr0 * 160 + 128 + c] =
                make_float2(d1[nt * 4 + 0] * inv0, d1[nt * 4 + 1] * inv0);
        }
        if (gr1 < N_NODES) {
            *(float2*)&out[gr1 * 160 + 128 + c] =
                make_float2(d1[nt * 4 + 2] * inv1, d1[nt * 4 + 3] * inv1);
        }
    }
}

// ---------------------------------------------------------------------------
extern "C" void kernel_launch(void* const* d_in, const int* in_sizes, int n_in,
                              void* d_out, int out_size)
{
    const float* user_tab = (const float*)d_in[0];
    const float* entity_tab = (const float*)d_in[1];
    const float* A_vals = (const float*)d_in[2];
    const float* W1_1 = (const float*)d_in[3];
    const float* b1_1 = (const float*)d_in[4];
    const float* W2_1 = (const float*)d_in[5];
    const float* b2_1 = (const float*)d_in[6];
    const float* W1_2 = (const float*)d_in[7];
    const float* b1_2 = (const float*)d_in[8];
    const float* W2_2 = (const float*)d_in[9];
    const float* b2_2 = (const float*)d_in[10];
    const int* A_rows = (const int*)d_in[11];
    const int* A_cols = (const int*)d_in[12];
    float* out = (float*)d_out;

    int eg = (N_EDGES + 255) / 256;

    void* cnt_ptr = nullptr;
    cudaGetSymbolAddress(&cnt_ptr, g_cnt);
    cudaMemsetAsync(cnt_ptr, 0, N_NODES * sizeof(int));
    void* st_ptr = nullptr;
    cudaGetSymbolAddress(&st_ptr, g_state);
    cudaMemsetAsync(st_ptr, 0, SCAN_NB * sizeof(ull));

    // 0: init
    k_init<<<(N_NODES * 16 + 255) / 256, 256>>>(
        (const float4*)user_tab, (const float4*)entity_tab, A_rows, (float4*)out);
    // 1: scan
    k_scan<<<SCAN_NB, SCAN_BS>>>();
    // 2: scatter
    k_scatter<<<eg, 256>>>(A_rows, A_cols, A_vals);
    // 3: fused layer 1 (tensor-core GEMM, smem-staged edges)
    k_layer1<<<(N_NODES + 63) / 64, 256>>>(W1_1, b1_1, W2_1, b2_1, out);
    // 4: fused layer 2
    k_layer2<<<(N_NODES + 63) / 64, 256>>>(W1_2, b1_2, W2_2, b2_2, out);
}

// round 13
// speedup vs baseline: 1.0959x; 1.0959x over previous
#include <cuda_runtime.h>
#include <cuda_fp16.h>
#include <cstdint>

#define N_USERS 30000
#define N_NODES 100000
#define N_EDGES 1600000

#define SCAN_BS 512
#define SCAN_NB ((N_NODES + SCAN_BS - 1) / SCAN_BS)   // 196
#define EDGE_CAP1 2304    // layer1 smem edge buffer (aliased with weight tiles)
#define EDGE_CAP2 1536    // layer2

typedef unsigned long long ull;

// Scratch
__device__ float4  g_egoA[N_NODES * 16];     // layer-0 ego fp32
__device__ float2  g_egoB[N_NODES * 32];     // layer-1 ego fp32
__device__ __half2 g_egoAh[N_NODES * 32];    // fp16 shadows (gather only)
__device__ __half2 g_egoBh[N_NODES * 32];
__device__ int  g_cnt[N_NODES];
__device__ int  g_off[N_NODES + 1];
__device__ int  g_cur[N_NODES];
__device__ ull  g_state[SCAN_NB];
__device__ int2 g_edges[N_EDGES];            // row-sorted (col, half2(v,v) bits)
// pre-converted fp16 weights in padded LDSM layout
__device__ __align__(16) __half g_w1hA[64 * 72];
__device__ __align__(16) __half g_w2hA[64 * 72];
__device__ __align__(16) __half g_w1hB[64 * 40];
__device__ __align__(16) __half g_w2hB[64 * 40];

__device__ __forceinline__ __half2 h2bits(int b) {
    __half2 h; *(int*)&h = b; return h;
}
__device__ __forceinline__ uint32_t smem_u32(const void* p) {
    return (uint32_t)__cvta_generic_to_shared(p);
}

#define LDSM_X4(r0, r1, r2, r3, addr) \
    asm volatile("ldmatrix.sync.aligned.m8n8.x4.shared.b16 {%0,%1,%2,%3}, [%4];" \
        : "=r"(r0), "=r"(r1), "=r"(r2), "=r"(r3) : "r"(addr))
#define LDSM_X2T(r0, r1, addr) \
    asm volatile("ldmatrix.sync.aligned.m8n8.x2.trans.shared.b16 {%0,%1}, [%2];" \
        : "=r"(r0), "=r"(r1) : "r"(addr))
#define MMA16816(d, a0, a1, a2, a3, b0, b1) \
    asm volatile("mma.sync.aligned.m16n8k16.row.col.f32.f16.f16.f32 " \
        "{%0,%1,%2,%3},{%4,%5,%6,%7},{%8,%9},{%0,%1,%2,%3};" \
        : "+f"((d)[0]), "+f"((d)[1]), "+f"((d)[2]), "+f"((d)[3]) \
        : "r"(a0), "r"(a1), "r"(a2), "r"(a3), "r"(b0), "r"(b1))

// ---------------------------------------------------------------------------
// k_init: ego0 (fp32 + fp16 shadow), out[:,0:64], edge histogram, fp16 weights.
// ---------------------------------------------------------------------------
__global__ __launch_bounds__(256) void k_init(
    const float4* __restrict__ user4,
    const float4* __restrict__ ent4,
    const int* __restrict__ rows,
    const float* __restrict__ W1_1, const float* __restrict__ W2_1,
    const float* __restrict__ W1_2, const float* __restrict__ W2_2,
    float4* __restrict__ out4)
{
    int idx = blockIdx.x * blockDim.x + threadIdx.x;
    if (idx < N_EDGES) atomicAdd(&g_cnt[rows[idx]], 1);
    if (idx < 4096) {
        int k = idx >> 6, n = idx & 63;
        g_w1hA[k * 72 + n] = __float2half(W1_1[idx]);
        g_w2hA[k * 72 + n] = __float2half(W2_1[idx]);
    } else if (idx < 4096 + 2048) {
        int t = idx - 4096;
        int k = t >> 5, n = t & 31;
        g_w1hB[k * 40 + n] = __float2half(W1_2[t]);
        g_w2hB[k * 40 + n] = __float2half(W2_2[t]);
    }
    if (idx >= N_NODES * 16) return;
    int row = idx >> 4;
    int part = idx & 15;
    float4 v = (row < N_USERS) ? user4[row * 16 + part]
                               : ent4[(row - N_USERS) * 16 + part];
    g_egoA[idx] = v;
    g_egoAh[row * 32 + 2 * part]     = __floats2half2_rn(v.x, v.y);
    g_egoAh[row * 32 + 2 * part + 1] = __floats2half2_rn(v.z, v.w);
    out4[row * 40 + part] = v;
}

// ---------------------------------------------------------------------------
// Single-pass exclusive scan (decoupled lookback).
// ---------------------------------------------------------------------------
__global__ __launch_bounds__(SCAN_BS) void k_scan()
{
    __shared__ int warp_sums[16];
    __shared__ int blk_prefix;

    int tid = threadIdx.x;
    int bid = blockIdx.x;
    int lane = tid & 31;
    int wid = tid >> 5;
    int i = bid * SCAN_BS + tid;
    int v = (i < N_NODES) ? g_cnt[i] : 0;

    int x = v;
    #pragma unroll
    for (int off = 1; off < 32; off <<= 1) {
        int t = __shfl_up_sync(0xFFFFFFFFu, x, off);
        if (lane >= off) x += t;
    }
    if (lane == 31) warp_sums[wid] = x;
    __syncthreads();
    if (wid == 0) {
        int s = (lane < 16) ? warp_sums[lane] : 0;
        #pragma unroll
        for (int off = 1; off < 16; off <<= 1) {
            int t = __shfl_up_sync(0xFFFFFFFFu, s, off);
            if (lane >= off) s += t;
        }
        if (lane < 16) warp_sums[lane] = s;
    }
    __syncthreads();
    int incl = x + (wid > 0 ? warp_sums[wid - 1] : 0);
    int block_total = warp_sums[15];

    if (tid == 0) {
        if (bid == 0) {
            atomicExch(&g_state[0], (2ULL << 32) | (unsigned)block_total);
            blk_prefix = 0;
        } else {
            atomicExch(&g_state[bid], (1ULL << 32) | (unsigned)block_total);
            int pref = 0;
            int j = bid - 1;
            while (true) {
                ull s = atomicAdd(&g_state[j], 0ULL);
                unsigned st = (unsigned)(s >> 32);
                if (st == 2) { pref += (int)(unsigned)s; break; }
                if (st == 1) { pref += (int)(unsigned)s; j--; }
            }
            atomicExch(&g_state[bid], (2ULL << 32) | (unsigned)(pref + block_total));
            blk_prefix = pref;
        }
    }
    __syncthreads();

    int excl = blk_prefix + incl - v;
    if (i < N_NODES) { g_off[i] = excl; g_cur[i] = excl; }
    if (i == N_NODES - 1) g_off[N_NODES] = N_EDGES;
}

__global__ __launch_bounds__(256) void k_scatter(
    const int* __restrict__ rows,
    const int* __restrict__ cols,
    const float* __restrict__ vals)
{
    int e = blockIdx.x * blockDim.x + threadIdx.x;
    if (e >= N_EDGES) return;
    int pos = atomicAdd(&g_cur[rows[e]], 1);
    float v = vals[e];
    __half2 vv = __floats2half2_rn(v, v);
    g_edges[pos] = make_int2(cols[e], *(const int*)&vv);
}

// ---------------------------------------------------------------------------
// Gather from GLOBAL descriptors (fallback path).
// ---------------------------------------------------------------------------
__device__ __forceinline__ void gather_row_g(
    const __half2* __restrict__ egoH, int lane, int s, int e,
    float& ax, float& ay)
{
    int i = s;
    if ((i & 1) && i < e) {
        int2 cv = g_edges[i];
        __half2 p = __hmul2(h2bits(cv.y), egoH[cv.x * 32 + lane]);
        float2 f = __half22float2(p);
        ax += f.x; ay += f.y;
        i++;
    }
    const int4* ep = (const int4*)g_edges;
    for (; i + 7 < e; i += 8) {
        int4 p0 = ep[(i >> 1) + 0];
        int4 p1 = ep[(i >> 1) + 1];
        int4 p2 = ep[(i >> 1) + 2];
        int4 p3 = ep[(i >> 1) + 3];
        __half2 x0 = egoH[p0.x * 32 + lane];
        __half2 x1 = egoH[p0.z * 32 + lane];
        __half2 x2 = egoH[p1.x * 32 + lane];
        __half2 x3 = egoH[p1.z * 32 + lane];
        __half2 x4 = egoH[p2.x * 32 + lane];
        __half2 x5 = egoH[p2.z * 32 + lane];
        __half2 x6 = egoH[p3.x * 32 + lane];
        __half2 x7 = egoH[p3.z * 32 + lane];
        __half2 acc = __hmul2(h2bits(p0.y), x0);
        acc = __hfma2(h2bits(p0.w), x1, acc);
        acc = __hfma2(h2bits(p1.y), x2, acc);
        acc = __hfma2(h2bits(p1.w), x3, acc);
        acc = __hfma2(h2bits(p2.y), x4, acc);
        acc = __hfma2(h2bits(p2.w), x5, acc);
        acc = __hfma2(h2bits(p3.y), x6, acc);
        acc = __hfma2(h2bits(p3.w), x7, acc);
        float2 f = __half22float2(acc);
        ax += f.x; ay += f.y;
    }
    for (; i < e; i++) {
        int2 cv = g_edges[i];
        __half2 p = __hmul2(h2bits(cv.y), egoH[cv.x * 32 + lane]);
        float2 f = __half22float2(p);
        ax += f.x; ay += f.y;
    }
}

// ---------------------------------------------------------------------------
// Gather from SMEM descriptors (s, e relative to block's edge window).
// ---------------------------------------------------------------------------
__device__ __forceinline__ void gather_row_s(
    const int2* __restrict__ sE,
    const __half2* __restrict__ egoH, int lane, int s, int e,
    float& ax, float& ay)
{
    int i = s;
    if ((i & 1) && i < e) {
        int2 cv = sE[i];
        __half2 p = __hmul2(h2bits(cv.y), egoH[cv.x * 32 + lane]);
        float2 f = __half22float2(p);
        ax += f.x; ay += f.y;
        i++;
    }
    const int4* ep = (const int4*)sE;
    for (; i + 7 < e; i += 8) {
        int4 p0 = ep[(i >> 1) + 0];
        int4 p1 = ep[(i >> 1) + 1];
        int4 p2 = ep[(i >> 1) + 2];
        int4 p3 = ep[(i >> 1) + 3];
        __half2 x0 = egoH[p0.x * 32 + lane];
        __half2 x1 = egoH[p0.z * 32 + lane];
        __half2 x2 = egoH[p1.x * 32 + lane];
        __half2 x3 = egoH[p1.z * 32 + lane];
        __half2 x4 = egoH[p2.x * 32 + lane];
        __half2 x5 = egoH[p2.z * 32 + lane];
        __half2 x6 = egoH[p3.x * 32 + lane];
        __half2 x7 = egoH[p3.z * 32 + lane];
        __half2 acc = __hmul2(h2bits(p0.y), x0);
        acc = __hfma2(h2bits(p0.w), x1, acc);
        acc = __hfma2(h2bits(p1.y), x2, acc);
        acc = __hfma2(h2bits(p1.w), x3, acc);
        acc = __hfma2(h2bits(p2.y), x4, acc);
        acc = __hfma2(h2bits(p2.w), x5, acc);
        acc = __hfma2(h2bits(p3.y), x6, acc);
        acc = __hfma2(h2bits(p3.w), x7, acc);
        float2 f = __half22float2(acc);
        ax += f.x; ay += f.y;
    }
    for (; i < e; i++) {
        int2 cv = sE[i];
        __half2 p = __hmul2(h2bits(cv.y), egoH[cv.x * 32 + lane]);
        float2 f = __half22float2(p);
        ax += f.x; ay += f.y;
    }
}

// ---------------------------------------------------------------------------
// Fused layer 1: edge stage -> gather (8 rows/warp) -> [weights overwrite the
// edge buffer] -> mma.sync GEMMs -> lrelu/sum/l2norm. Block = 64 rows.
// smem: sA 9216 | sM 9216 | union(sE 18432 / sW1 9216 + sW2 9216) | sP 512
// ---------------------------------------------------------------------------
__global__ __launch_bounds__(256, 5) void k_layer1(
    const float* __restrict__ b1, const float* __restrict__ b2,
    float* __restrict__ out)
{
    __shared__ __align__(16) char smem_raw[9216 * 2 + 18432 + 512];
    __half* sA = (__half*)smem_raw;
    __half* sM = (__half*)(smem_raw + 9216);
    int2*   sE = (int2*)(smem_raw + 18432);
    __half* sW1 = (__half*)(smem_raw + 18432);
    __half* sW2 = (__half*)(smem_raw + 18432 + 9216);
    float (*sP)[2] = (float(*)[2])(smem_raw + 36864);

    int tid = threadIdx.x;
    int wid = tid >> 5;
    int lane = tid & 31;
    int rbase = blockIdx.x * 64;
    int rend = min(rbase + 64, N_NODES);

    if (rbase + 64 > N_NODES) {
        for (int i = tid; i < 64 * 36; i += 256) {
            ((uint32_t*)sA)[i] = 0;
            ((uint32_t*)sM)[i] = 0;
        }
    }
    // stage this block's edge window (contiguous, coalesced)
    int ebase = g_off[rbase];
    int etotal = g_off[rend] - ebase;
    bool use_smem = (etotal <= EDGE_CAP1);
    if (use_smem) {
        for (int i = tid; i < etotal; i += 256)
            sE[i] = g_edges[ebase + i];
    }
    __syncthreads();

    // gather phase: warp handles rows [wid*8, wid*8+8)
    const float2* egoA2 = (const float2*)g_egoA;
    for (int rr = 0; rr < 8; rr++) {
        int lrow = wid * 8 + rr;
        int r = rbase + lrow;
        if (r < N_NODES) {
            int s = g_off[r], e = g_off[r + 1];
            float ax = 0.f, ay = 0.f;
            if (use_smem) gather_row_s(sE, g_egoAh, lane, s - ebase, e - ebase, ax, ay);
            else          gather_row_g(g_egoAh, lane, s, e, ax, ay);
            float2 eg = egoA2[r * 32 + lane];
            *(__half2*)&sA[lrow * 72 + 2 * lane] = __floats2half2_rn(eg.x + ax, eg.y + ay);
            *(__half2*)&sM[lrow * 72 + 2 * lane] = __floats2half2_rn(eg.x * ax, eg.y * ay);
        }
    }
    __syncthreads();

    // weights overwrite the (dead) edge buffer: plain int4 copy of packed fp16
    for (int i = tid; i < 576; i += 256) {
        ((int4*)sW1)[i] = ((const int4*)g_w1hA)[i];
        ((int4*)sW2)[i] = ((const int4*)g_w2hA)[i];
    }
    __syncthreads();

    // mma phase
    int t = wid >> 1;
    int h = wid & 1;

    float d1[16], d2[16];
    #pragma unroll
    for (int nt = 0; nt < 4; nt++) {
        int c = h * 32 + nt * 8 + (lane & 3) * 2;
        float bb1a = b1[c], bb1b = b1[c + 1];
        float bb2a = b2[c], bb2b = b2[c + 1];
        d1[nt * 4 + 0] = bb1a; d1[nt * 4 + 1] = bb1b;
        d1[nt * 4 + 2] = bb1a; d1[nt * 4 + 3] = bb1b;
        d2[nt * 4 + 0] = bb2a; d2[nt * 4 + 1] = bb2b;
        d2[nt * 4 + 2] = bb2a; d2[nt * 4 + 3] = bb2b;
    }

    int q = lane >> 3;
    int ri = lane & 7;
    int arow = t * 16 + (q & 1) * 8 + ri;
    int acol = (q >> 1) * 8;
    uint32_t aA = smem_u32(&sA[arow * 72 + acol]);
    uint32_t aM = smem_u32(&sM[arow * 72 + acol]);
    int g2 = q & 1;
    uint32_t bW1 = smem_u32(&sW1[(g2 * 8 + ri) * 72 + h * 32]);
    uint32_t bW2 = smem_u32(&sW2[(g2 * 8 + ri) * 72 + h * 32]);

    #pragma unroll
    for (int ks = 0; ks < 4; ks++) {
        uint32_t a0, a1, a2, a3;
        LDSM_X4(a0, a1, a2, a3, aA + ks * 32);
        #pragma unroll
        for (int nt = 0; nt < 4; nt++) {
            uint32_t b0, b1r;
            LDSM_X2T(b0, b1r, bW1 + ks * 16 * 144 + nt * 16);
            MMA16816(&d1[nt * 4], a0, a1, a2, a3, b0, b1r);
        }
        LDSM_X4(a0, a1, a2, a3, aM + ks * 32);
        #pragma unroll
        for (int nt = 0; nt < 4; nt++) {
            uint32_t b0, b1r;
            LDSM_X2T(b0, b1r, bW2 + ks * 16 * 144 + nt * 16);
            MMA16816(&d2[nt * 4], a0, a1, a2, a3, b0, b1r);
        }
    }

    // epilogue
    float ss0 = 0.f, ss1 = 0.f;
    #pragma unroll
    for (int nt = 0; nt < 4; nt++) {
        #pragma unroll
        for (int i = 0; i < 4; i++) {
            float v1 = d1[nt * 4 + i], v2 = d2[nt * 4 + i];
            float v = (v1 > 0.f ? v1 : 0.01f * v1) + (v2 > 0.f ? v2 : 0.01f * v2);
            d1[nt * 4 + i] = v;
            if (i < 2) ss0 += v * v; else ss1 += v * v;
        }
    }
    ss0 += __shfl_xor_sync(0xFFFFFFFFu, ss0, 1);
    ss0 += __shfl_xor_sync(0xFFFFFFFFu, ss0, 2);
    ss1 += __shfl_xor_sync(0xFFFFFFFFu, ss1, 1);
    ss1 += __shfl_xor_sync(0xFFFFFFFFu, ss1, 2);
    if ((lane & 3) == 0) {
        sP[t * 16 + (lane >> 2)][h] = ss0;
        sP[t * 16 + (lane >> 2) + 8][h] = ss1;
    }
    __syncthreads();

    int r0 = t * 16 + (lane >> 2);
    int r1 = r0 + 8;
    float inv0 = 1.f / fmaxf(sqrtf(sP[r0][0] + sP[r0][1]), 1e-12f);
    float inv1 = 1.f / fmaxf(sqrtf(sP[r1][0] + sP[r1][1]), 1e-12f);
    int gr0 = rbase + r0, gr1 = rbase + r1;
    #pragma unroll
    for (int nt = 0; nt < 4; nt++) {
        int c = h * 32 + nt * 8 + (lane & 3) * 2;
        if (gr0 < N_NODES) {
            float x0 = d1[nt * 4 + 0] * inv0, x1 = d1[nt * 4 + 1] * inv0;
            *(float2*)&out[gr0 * 160 + 64 + c] = make_float2(x0, x1);
            g_egoB[gr0 * 32 + (c >> 1)] = make_float2(x0, x1);
            g_egoBh[gr0 * 32 + (c >> 1)] = __floats2half2_rn(x0, x1);
        }
        if (gr1 < N_NODES) {
            float x0 = d1[nt * 4 + 2] * inv1, x1 = d1[nt * 4 + 3] * inv1;
            *(float2*)&out[gr1 * 160 + 64 + c] = make_float2(x0, x1);
            g_egoB[gr1 * 32 + (c >> 1)] = make_float2(x0, x1);
            g_egoBh[gr1 * 32 + (c >> 1)] = __floats2half2_rn(x0, x1);
        }
    }
}

// ---------------------------------------------------------------------------
// Fused layer 2: same structure, N=32.
// smem: sA 9216 | sM 9216 | union(sE 12288 / sW1 5120 + sW2 5120) | sP 512
// ---------------------------------------------------------------------------
__global__ __launch_bounds__(256, 5) void k_layer2(
    const float* __restrict__ b1, const float* __restrict__ b2,
    float* __restrict__ out)
{
    __shared__ __align__(16) char smem_raw[9216 * 2 + 12288 + 512];
    __half* sA = (__half*)smem_raw;
    __half* sM = (__half*)(smem_raw + 9216);
    int2*   sE = (int2*)(smem_raw + 18432);
    __half* sW1 = (__half*)(smem_raw + 18432);
    __half* sW2 = (__half*)(smem_raw + 18432 + 5120);
    float (*sP)[2] = (float(*)[2])(smem_raw + 18432 + 12288);

    int tid = threadIdx.x;
    int wid = tid >> 5;
    int lane = tid & 31;
    int rbase = blockIdx.x * 64;
    int rend = min(rbase + 64, N_NODES);

    if (rbase + 64 > N_NODES) {
        for (int i = tid; i < 64 * 36; i += 256) {
            ((uint32_t*)sA)[i] = 0;
            ((uint32_t*)sM)[i] = 0;
        }
    }
    int ebase = g_off[rbase];
    int etotal = g_off[rend] - ebase;
    bool use_smem = (etotal <= EDGE_CAP2);
    if (use_smem) {
        for (int i = tid; i < etotal; i += 256)
            sE[i] = g_edges[ebase + i];
    }
    __syncthreads();

    for (int rr = 0; rr < 8; rr++) {
        int lrow = wid * 8 + rr;
        int r = rbase + lrow;
        if (r < N_NODES) {
            int s = g_off[r], e = g_off[r + 1];
            float ax = 0.f, ay = 0.f;
            if (use_smem) gather_row_s(sE, g_egoBh, lane, s - ebase, e - ebase, ax, ay);
            else          gather_row_g(g_egoBh, lane, s, e, ax, ay);
            float2 eg = g_egoB[r * 32 + lane];
            *(__half2*)&sA[lrow * 72 + 2 * lane] = __floats2half2_rn(eg.x + ax, eg.y + ay);
            *(__half2*)&sM[lrow * 72 + 2 * lane] = __floats2half2_rn(eg.x * ax, eg.y * ay);
        }
    }
    __syncthreads();

    for (int i = tid; i < 320; i += 256) {
        ((int4*)sW1)[i] = ((const int4*)g_w1hB)[i];
        ((int4*)sW2)[i] = ((const int4*)g_w2hB)[i];
    }
    __syncthreads();

    int t = wid >> 1;
    int h = wid & 1;

    float d1[8], d2[8];
    #pragma unroll
    for (int nt = 0; nt < 2; nt++) {
        int c = h * 16 + nt * 8 + (lane & 3) * 2;
        float bb1a = b1[c], bb1b = b1[c + 1];
        float bb2a = b2[c], bb2b = b2[c + 1];
        d1[nt * 4 + 0] = bb1a; d1[nt * 4 + 1] = bb1b;
        d1[nt * 4 + 2] = bb1a; d1[nt * 4 + 3] = bb1b;
        d2[nt * 4 + 0] = bb2a; d2[nt * 4 + 1] = bb2b;
        d2[nt * 4 + 2] = bb2a; d2[nt * 4 + 3] = bb2b;
    }

    int q = lane >> 3;
    int ri = lane & 7;
    int arow = t * 16 + (q & 1) * 8 + ri;
    int acol = (q >> 1) * 8;
    uint32_t aA = smem_u32(&sA[arow * 72 + acol]);
    uint32_t aM = smem_u32(&sM[arow * 72 + acol]);
    int g2 = q & 1;
    uint32_t bW1 = smem_u32(&sW1[(g2 * 8 + ri) * 40 + h * 16]);
    uint32_t bW2 = smem_u32(&sW2[(g2 * 8 + ri) * 40 + h * 16]);

    #pragma unroll
    for (int ks = 0; ks < 4; ks++) {
        uint32_t a0, a1, a2, a3;
        LDSM_X4(a0, a1, a2, a3, aA + ks * 32);
        #pragma unroll
        for (int nt = 0; nt < 2; nt++) {
            uint32_t b0, b1r;
            LDSM_X2T(b0, b1r, bW1 + ks * 16 * 80 + nt * 16);
            MMA16816(&d1[nt * 4], a0, a1, a2, a3, b0, b1r);
        }
        LDSM_X4(a0, a1, a2, a3, aM + ks * 32);
        #pragma unroll
        for (int nt = 0; nt < 2; nt++) {
            uint32_t b0, b1r;
            LDSM_X2T(b0, b1r, bW2 + ks * 16 * 80 + nt * 16);
            MMA16816(&d2[nt * 4], a0, a1, a2, a3, b0, b1r);
        }
    }

    float ss0 = 0.f, ss1 = 0.f;
    #pragma unroll
    for (int nt = 0; nt < 2; nt++) {
        #pragma unroll
        for (int i = 0; i < 4; i++) {
            float v1 = d1[nt * 4 + i], v2 = d2[nt * 4 + i];
            float v = (v1 > 0.f ? v1 : 0.01f * v1) + (v2 > 0.f ? v2 : 0.01f * v2);
            d1[nt * 4 + i] = v;
            if (i < 2) ss0 += v * v; else ss1 += v * v;
        }
    }
    ss0 += __shfl_xor_sync(0xFFFFFFFFu, ss0, 1);
    ss0 += __shfl_xor_sync(0xFFFFFFFFu, ss0, 2);
    ss1 += __shfl_xor_sync(0xFFFFFFFFu, ss1, 1);
    ss1 += __shfl_xor_sync(0xFFFFFFFFu, ss1, 2);
    if ((lane & 3) == 0) {
        sP[t * 16 + (lane >> 2)][h] = ss0;
        sP[t * 16 + (lane >> 2) + 8][h] = ss1;
    }
    __syncthreads();

    int r0 = t * 16 + (lane >> 2);
    int r1 = r0 + 8;
    float inv0 = 1.f / fmaxf(sqrtf(sP[r0][0] + sP[r0][1]), 1e-12f);
    float inv1 = 1.f / fmaxf(sqrtf(sP[r1][0] + sP[r1][1]), 1e-12f);
    int gr0 = rbase + r0, gr1 = rbase + r1;
    #pragma unroll
    for (int nt = 0; nt < 2; nt++) {
        int c = h * 16 + nt * 8 + (lane & 3) * 2;
        if (gr0 < N_NODES) {
            *(float2*)&out[gr0 * 160 + 128 + c] =
                make_float2(d1[nt * 4 + 0] * inv0, d1[nt * 4 + 1] * inv0);
        }
        if (gr1 < N_NODES) {
            *(float2*)&out[gr1 * 160 + 128 + c] =
                make_float2(d1[nt * 4 + 2] * inv1, d1[nt * 4 + 3] * inv1);
        }
    }
}

// ---------------------------------------------------------------------------
extern "C" void kernel_launch(void* const* d_in, const int* in_sizes, int n_in,
                              void* d_out, int out_size)
{
    const float* user_tab = (const float*)d_in[0];
    const float* entity_tab = (const float*)d_in[1];
    const float* A_vals = (const float*)d_in[2];
    const float* W1_1 = (const float*)d_in[3];
    const float* b1_1 = (const float*)d_in[4];
    const float* W2_1 = (const float*)d_in[5];
    const float* b2_1 = (const float*)d_in[6];
    const float* W1_2 = (const float*)d_in[7];
    const float* b1_2 = (const float*)d_in[8];
    const float* W2_2 = (const float*)d_in[9];
    const float* b2_2 = (const float*)d_in[10];
    const int* A_rows = (const int*)d_in[11];
    const int* A_cols = (const int*)d_in[12];
    float* out = (float*)d_out;

    int eg = (N_EDGES + 255) / 256;

    void* cnt_ptr = nullptr;
    cudaGetSymbolAddress(&cnt_ptr, g_cnt);
    cudaMemsetAsync(cnt_ptr, 0, N_NODES * sizeof(int));
    void* st_ptr = nullptr;
    cudaGetSymbolAddress(&st_ptr, g_state);
    cudaMemsetAsync(st_ptr, 0, SCAN_NB * sizeof(ull));

    // 0: init (ego + out[:,0:64] + histogram + fp16 weight pack)
    k_init<<<(N_NODES * 16 + 255) / 256, 256>>>(
        (const float4*)user_tab, (const float4*)entity_tab, A_rows,
        W1_1, W2_1, W1_2, W2_2, (float4*)out);
    // 1: scan
    k_scan<<<SCAN_NB, SCAN_BS>>>();
    // 2: scatter
    k_scatter<<<eg, 256>>>(A_rows, A_cols, A_vals);
    // 3: fused layer 1 (tensor-core GEMM, smem-staged edges, aliased weights)
    k_layer1<<<(N_NODES + 63) / 64, 256>>>(b1_1, b2_1, out);
    // 4: fused layer 2
    k_layer2<<<(N_NODES + 63) / 64, 256>>>(b1_2, b2_2, out);
}

// round 14
// speedup vs baseline: 1.1711x; 1.0686x over previous
#include <cuda_runtime.h>
#include <cuda_fp16.h>
#include <cstdint>

#define N_USERS 30000
#define N_NODES 100000
#define N_EDGES 1600000

#define SCAN_BS 512
#define SCAN_NB ((N_NODES + SCAN_BS - 1) / SCAN_BS)   // 196
#define EDGE_CAP1 2304    // layer1 smem edge buffer (aliased with weight tiles)
#define EDGE_CAP2 1536    // layer2

typedef unsigned long long ull;

// Scratch
__device__ float4  g_egoA[N_NODES * 16];     // layer-0 ego fp32
__device__ float2  g_egoB[N_NODES * 32];     // layer-1 ego fp32
__device__ __half2 g_egoAh[N_NODES * 32];    // fp16 shadows (gather only)
__device__ __half2 g_egoBh[N_NODES * 32];
__device__ int  g_cnt[N_NODES];
__device__ int  g_off[N_NODES + 1];
__device__ int  g_cur[N_NODES];
__device__ ull  g_state[SCAN_NB];
__device__ int2 g_edges[N_EDGES];            // row-sorted (col, half2(v,v) bits)
// pre-converted fp16 weights in padded LDSM layout
__device__ __align__(16) __half g_w1hA[64 * 72];
__device__ __align__(16) __half g_w2hA[64 * 72];
__device__ __align__(16) __half g_w1hB[64 * 40];
__device__ __align__(16) __half g_w2hB[64 * 40];

__device__ __forceinline__ __half2 h2bits(int b) {
    __half2 h; *(int*)&h = b; return h;
}
__device__ __forceinline__ uint32_t smem_u32(const void* p) {
    return (uint32_t)__cvta_generic_to_shared(p);
}

#define LDSM_X4(r0, r1, r2, r3, addr) \
    asm volatile("ldmatrix.sync.aligned.m8n8.x4.shared.b16 {%0,%1,%2,%3}, [%4];" \
        : "=r"(r0), "=r"(r1), "=r"(r2), "=r"(r3) : "r"(addr))
#define LDSM_X2T(r0, r1, addr) \
    asm volatile("ldmatrix.sync.aligned.m8n8.x2.trans.shared.b16 {%0,%1}, [%2];" \
        : "=r"(r0), "=r"(r1) : "r"(addr))
#define MMA16816(d, a0, a1, a2, a3, b0, b1) \
    asm volatile("mma.sync.aligned.m16n8k16.row.col.f32.f16.f16.f32 " \
        "{%0,%1,%2,%3},{%4,%5,%6,%7},{%8,%9},{%0,%1,%2,%3};" \
        : "+f"((d)[0]), "+f"((d)[1]), "+f"((d)[2]), "+f"((d)[3]) \
        : "r"(a0), "r"(a1), "r"(a2), "r"(a3), "r"(b0), "r"(b1))

// ---------------------------------------------------------------------------
// k_init: ego0 (fp32 + fp16 shadow), out[:,0:64], edge histogram, fp16 weights.
// ---------------------------------------------------------------------------
__global__ __launch_bounds__(256) void k_init(
    const float4* __restrict__ user4,
    const float4* __restrict__ ent4,
    const int* __restrict__ rows,
    const float* __restrict__ W1_1, const float* __restrict__ W2_1,
    const float* __restrict__ W1_2, const float* __restrict__ W2_2,
    float4* __restrict__ out4)
{
    int idx = blockIdx.x * blockDim.x + threadIdx.x;
    if (idx < N_EDGES) atomicAdd(&g_cnt[rows[idx]], 1);
    if (idx < 4096) {
        int k = idx >> 6, n = idx & 63;
        g_w1hA[k * 72 + n] = __float2half(W1_1[idx]);
        g_w2hA[k * 72 + n] = __float2half(W2_1[idx]);
    } else if (idx < 4096 + 2048) {
        int t = idx - 4096;
        int k = t >> 5, n = t & 31;
        g_w1hB[k * 40 + n] = __float2half(W1_2[t]);
        g_w2hB[k * 40 + n] = __float2half(W2_2[t]);
    }
    if (idx >= N_NODES * 16) return;
    int row = idx >> 4;
    int part = idx & 15;
    float4 v = (row < N_USERS) ? user4[row * 16 + part]
                               : ent4[(row - N_USERS) * 16 + part];
    g_egoA[idx] = v;
    g_egoAh[row * 32 + 2 * part]     = __floats2half2_rn(v.x, v.y);
    g_egoAh[row * 32 + 2 * part + 1] = __floats2half2_rn(v.z, v.w);
    out4[row * 40 + part] = v;
}

// ---------------------------------------------------------------------------
// Single-pass exclusive scan (decoupled lookback).
// ---------------------------------------------------------------------------
__global__ __launch_bounds__(SCAN_BS) void k_scan()
{
    __shared__ int warp_sums[16];
    __shared__ int blk_prefix;

    int tid = threadIdx.x;
    int bid = blockIdx.x;
    int lane = tid & 31;
    int wid = tid >> 5;
    int i = bid * SCAN_BS + tid;
    int v = (i < N_NODES) ? g_cnt[i] : 0;

    int x = v;
    #pragma unroll
    for (int off = 1; off < 32; off <<= 1) {
        int t = __shfl_up_sync(0xFFFFFFFFu, x, off);
        if (lane >= off) x += t;
    }
    if (lane == 31) warp_sums[wid] = x;
    __syncthreads();
    if (wid == 0) {
        int s = (lane < 16) ? warp_sums[lane] : 0;
        #pragma unroll
        for (int off = 1; off < 16; off <<= 1) {
            int t = __shfl_up_sync(0xFFFFFFFFu, s, off);
            if (lane >= off) s += t;
        }
        if (lane < 16) warp_sums[lane] = s;
    }
    __syncthreads();
    int incl = x + (wid > 0 ? warp_sums[wid - 1] : 0);
    int block_total = warp_sums[15];

    if (tid == 0) {
        if (bid == 0) {
            atomicExch(&g_state[0], (2ULL << 32) | (unsigned)block_total);
            blk_prefix = 0;
        } else {
            atomicExch(&g_state[bid], (1ULL << 32) | (unsigned)block_total);
            int pref = 0;
            int j = bid - 1;
            while (true) {
                ull s = atomicAdd(&g_state[j], 0ULL);
                unsigned st = (unsigned)(s >> 32);
                if (st == 2) { pref += (int)(unsigned)s; break; }
                if (st == 1) { pref += (int)(unsigned)s; j--; }
            }
            atomicExch(&g_state[bid], (2ULL << 32) | (unsigned)(pref + block_total));
            blk_prefix = pref;
        }
    }
    __syncthreads();

    int excl = blk_prefix + incl - v;
    if (i < N_NODES) { g_off[i] = excl; g_cur[i] = excl; }
    if (i == N_NODES - 1) g_off[N_NODES] = N_EDGES;
}

__global__ __launch_bounds__(256) void k_scatter(
    const int* __restrict__ rows,
    const int* __restrict__ cols,
    const float* __restrict__ vals)
{
    int e = blockIdx.x * blockDim.x + threadIdx.x;
    if (e >= N_EDGES) return;
    int pos = atomicAdd(&g_cur[rows[e]], 1);
    float v = vals[e];
    __half2 vv = __floats2half2_rn(v, v);
    g_edges[pos] = make_int2(cols[e], *(const int*)&vv);
}

// ---------------------------------------------------------------------------
// Tail gather for one row (index already even-aligned). 8-edge groups + scalar.
// ---------------------------------------------------------------------------
__device__ __forceinline__ void gather_tail(
    const int2* __restrict__ E, const __half2* __restrict__ egoH, int lane,
    int i, int e, float& ax, float& ay)
{
    const int4* ep = (const int4*)E;
    for (; i + 7 < e; i += 8) {
        int4 p0 = ep[(i >> 1) + 0];
        int4 p1 = ep[(i >> 1) + 1];
        int4 p2 = ep[(i >> 1) + 2];
        int4 p3 = ep[(i >> 1) + 3];
        __half2 x0 = egoH[p0.x * 32 + lane];
        __half2 x1 = egoH[p0.z * 32 + lane];
        __half2 x2 = egoH[p1.x * 32 + lane];
        __half2 x3 = egoH[p1.z * 32 + lane];
        __half2 x4 = egoH[p2.x * 32 + lane];
        __half2 x5 = egoH[p2.z * 32 + lane];
        __half2 x6 = egoH[p3.x * 32 + lane];
        __half2 x7 = egoH[p3.z * 32 + lane];
        __half2 acc = __hmul2(h2bits(p0.y), x0);
        acc = __hfma2(h2bits(p0.w), x1, acc);
        acc = __hfma2(h2bits(p1.y), x2, acc);
        acc = __hfma2(h2bits(p1.w), x3, acc);
        __half2 acc2 = __hmul2(h2bits(p2.y), x4);
        acc2 = __hfma2(h2bits(p2.w), x5, acc2);
        acc2 = __hfma2(h2bits(p3.y), x6, acc2);
        acc2 = __hfma2(h2bits(p3.w), x7, acc2);
        float2 f = __half22float2(acc);
        ax += f.x; ay += f.y;
        f = __half22float2(acc2);
        ax += f.x; ay += f.y;
    }
    for (; i < e; i++) {
        int2 cv = E[i];
        __half2 p = __hmul2(h2bits(cv.y), egoH[cv.x * 32 + lane]);
        float2 f = __half22float2(p);
        ax += f.x; ay += f.y;
    }
}

// ---------------------------------------------------------------------------
// Interleaved 2-row gather: per iteration, 4 descriptors + 8 gather loads
// covering TWO independent accumulation chains (4 edges per row). All loads
// issue before any consumption -> when the warp stalls on row0's HFMA2s,
// row1's gathers are already in flight.
// ---------------------------------------------------------------------------
__device__ __forceinline__ void gather_pair(
    const int2* __restrict__ E, const __half2* __restrict__ egoH, int lane,
    int i0, int e0, int i1, int e1,
    float& ax0, float& ay0, float& ax1, float& ay1)
{
    if (i0 < e0 && (i0 & 1)) {
        int2 cv = E[i0];
        __half2 p = __hmul2(h2bits(cv.y), egoH[cv.x * 32 + lane]);
        float2 f = __half22float2(p);
        ax0 += f.x; ay0 += f.y;
        i0++;
    }
    if (i1 < e1 && (i1 & 1)) {
        int2 cv = E[i1];
        __half2 p = __hmul2(h2bits(cv.y), egoH[cv.x * 32 + lane]);
        float2 f = __half22float2(p);
        ax1 += f.x; ay1 += f.y;
        i1++;
    }
    const int4* ep = (const int4*)E;
    while (i0 + 3 < e0 && i1 + 3 < e1) {
        int4 c00 = ep[i0 >> 1];
        int4 c01 = ep[(i0 >> 1) + 1];
        int4 c10 = ep[i1 >> 1];
        int4 c11 = ep[(i1 >> 1) + 1];
        __half2 x0 = egoH[c00.x * 32 + lane];
        __half2 x1 = egoH[c00.z * 32 + lane];
        __half2 x2 = egoH[c01.x * 32 + lane];
        __half2 x3 = egoH[c01.z * 32 + lane];
        __half2 y0 = egoH[c10.x * 32 + lane];
        __half2 y1 = egoH[c10.z * 32 + lane];
        __half2 y2 = egoH[c11.x * 32 + lane];
        __half2 y3 = egoH[c11.z * 32 + lane];
        __half2 a = __hmul2(h2bits(c00.y), x0);
        a = __hfma2(h2bits(c00.w), x1, a);
        a = __hfma2(h2bits(c01.y), x2, a);
        a = __hfma2(h2bits(c01.w), x3, a);
        float2 f = __half22float2(a);
        ax0 += f.x; ay0 += f.y;
        __half2 b = __hmul2(h2bits(c10.y), y0);
        b = __hfma2(h2bits(c10.w), y1, b);
        b = __hfma2(h2bits(c11.y), y2, b);
        b = __hfma2(h2bits(c11.w), y3, b);
        f = __half22float2(b);
        ax1 += f.x; ay1 += f.y;
        i0 += 4; i1 += 4;
    }
    gather_tail(E, egoH, lane, i0, e0, ax0, ay0);
    gather_tail(E, egoH, lane, i1, e1, ax1, ay1);
}

// ---------------------------------------------------------------------------
// Fused layer 1: edge stage -> interleaved pair gather (8 rows/warp) ->
// [weights overwrite the edge buffer] -> mma.sync GEMMs -> lrelu/sum/l2norm.
// smem: sA 9216 | sM 9216 | union(sE 18432 / sW1 9216 + sW2 9216) | sP 512
// ---------------------------------------------------------------------------
__global__ __launch_bounds__(256, 5) void k_layer1(
    const float* __restrict__ b1, const float* __restrict__ b2,
    float* __restrict__ out)
{
    __shared__ __align__(16) char smem_raw[9216 * 2 + 18432 + 512];
    __half* sA = (__half*)smem_raw;
    __half* sM = (__half*)(smem_raw + 9216);
    int2*   sE = (int2*)(smem_raw + 18432);
    __half* sW1 = (__half*)(smem_raw + 18432);
    __half* sW2 = (__half*)(smem_raw + 18432 + 9216);
    float (*sP)[2] = (float(*)[2])(smem_raw + 36864);

    int tid = threadIdx.x;
    int wid = tid >> 5;
    int lane = tid & 31;
    int rbase = blockIdx.x * 64;
    int rend = min(rbase + 64, N_NODES);

    if (rbase + 64 > N_NODES) {
        for (int i = tid; i < 64 * 36; i += 256) {
            ((uint32_t*)sA)[i] = 0;
            ((uint32_t*)sM)[i] = 0;
        }
    }
    // stage this block's edge window (contiguous, coalesced)
    int ebase = g_off[rbase];
    int etotal = g_off[rend] - ebase;
    bool use_smem = (etotal <= EDGE_CAP1);
    if (use_smem) {
        for (int i = tid; i < etotal; i += 256)
            sE[i] = g_edges[ebase + i];
    }
    __syncthreads();

    // gather phase: warp handles rows [wid*8, wid*8+8), two at a time
    const float2* egoA2 = (const float2*)g_egoA;
    for (int rr = 0; rr < 8; rr += 2) {
        int lrow = wid * 8 + rr;
        int r0 = rbase + lrow;
        if (r0 >= N_NODES) break;
        int r1 = r0 + 1;
        bool v1 = (r1 < N_NODES);
        int s0 = g_off[r0], e0 = g_off[r0 + 1];
        int s1 = v1 ? g_off[r1] : 0, e1 = v1 ? g_off[r1 + 1] : 0;
        float ax0 = 0.f, ay0 = 0.f, ax1 = 0.f, ay1 = 0.f;
        if (use_smem) {
            int rs1 = v1 ? s1 - ebase : 0, re1 = v1 ? e1 - ebase : 0;
            gather_pair(sE, g_egoAh, lane, s0 - ebase, e0 - ebase, rs1, re1,
                        ax0, ay0, ax1, ay1);
        } else {
            gather_pair(g_edges, g_egoAh, lane, s0, e0, s1, e1,
                        ax0, ay0, ax1, ay1);
        }
        float2 eg = egoA2[r0 * 32 + lane];
        *(__half2*)&sA[lrow * 72 + 2 * lane] = __floats2half2_rn(eg.x + ax0, eg.y + ay0);
        *(__half2*)&sM[lrow * 72 + 2 * lane] = __floats2half2_rn(eg.x * ax0, eg.y * ay0);
        if (v1) {
            float2 eg1 = egoA2[r1 * 32 + lane];
            *(__half2*)&sA[(lrow + 1) * 72 + 2 * lane] = __floats2half2_rn(eg1.x + ax1, eg1.y + ay1);
            *(__half2*)&sM[(lrow + 1) * 72 + 2 * lane] = __floats2half2_rn(eg1.x * ax1, eg1.y * ay1);
        }
    }
    __syncthreads();

    // weights overwrite the (dead) edge buffer: plain int4 copy of packed fp16
    for (int i = tid; i < 576; i += 256) {
        ((int4*)sW1)[i] = ((const int4*)g_w1hA)[i];
        ((int4*)sW2)[i] = ((const int4*)g_w2hA)[i];
    }
    __syncthreads();

    // mma phase
    int t = wid >> 1;
    int h = wid & 1;

    float d1[16], d2[16];
    #pragma unroll
    for (int nt = 0; nt < 4; nt++) {
        int c = h * 32 + nt * 8 + (lane & 3) * 2;
        float bb1a = b1[c], bb1b = b1[c + 1];
        float bb2a = b2[c], bb2b = b2[c + 1];
        d1[nt * 4 + 0] = bb1a; d1[nt * 4 + 1] = bb1b;
        d1[nt * 4 + 2] = bb1a; d1[nt * 4 + 3] = bb1b;
        d2[nt * 4 + 0] = bb2a; d2[nt * 4 + 1] = bb2b;
        d2[nt * 4 + 2] = bb2a; d2[nt * 4 + 3] = bb2b;
    }

    int q = lane >> 3;
    int ri = lane & 7;
    int arow = t * 16 + (q & 1) * 8 + ri;
    int acol = (q >> 1) * 8;
    uint32_t aA = smem_u32(&sA[arow * 72 + acol]);
    uint32_t aM = smem_u32(&sM[arow * 72 + acol]);
    int g2 = q & 1;
    uint32_t bW1 = smem_u32(&sW1[(g2 * 8 + ri) * 72 + h * 32]);
    uint32_t bW2 = smem_u32(&sW2[(g2 * 8 + ri) * 72 + h * 32]);

    #pragma unroll
    for (int ks = 0; ks < 4; ks++) {
        uint32_t a0, a1, a2, a3;
        LDSM_X4(a0, a1, a2, a3, aA + ks * 32);
        #pragma unroll
        for (int nt = 0; nt < 4; nt++) {
            uint32_t b0, b1r;
            LDSM_X2T(b0, b1r, bW1 + ks * 16 * 144 + nt * 16);
            MMA16816(&d1[nt * 4], a0, a1, a2, a3, b0, b1r);
        }
        LDSM_X4(a0, a1, a2, a3, aM + ks * 32);
        #pragma unroll
        for (int nt = 0; nt < 4; nt++) {
            uint32_t b0, b1r;
            LDSM_X2T(b0, b1r, bW2 + ks * 16 * 144 + nt * 16);
            MMA16816(&d2[nt * 4], a0, a1, a2, a3, b0, b1r);
        }
    }

    // epilogue
    float ss0 = 0.f, ss1 = 0.f;
    #pragma unroll
    for (int nt = 0; nt < 4; nt++) {
        #pragma unroll
        for (int i = 0; i < 4; i++) {
            float v1 = d1[nt * 4 + i], v2 = d2[nt * 4 + i];
            float v = (v1 > 0.f ? v1 : 0.01f * v1) + (v2 > 0.f ? v2 : 0.01f * v2);
            d1[nt * 4 + i] = v;
            if (i < 2) ss0 += v * v; else ss1 += v * v;
        }
    }
    ss0 += __shfl_xor_sync(0xFFFFFFFFu, ss0, 1);
    ss0 += __shfl_xor_sync(0xFFFFFFFFu, ss0, 2);
    ss1 += __shfl_xor_sync(0xFFFFFFFFu, ss1, 1);
    ss1 += __shfl_xor_sync(0xFFFFFFFFu, ss1, 2);
    if ((lane & 3) == 0) {
        sP[t * 16 + (lane >> 2)][h] = ss0;
        sP[t * 16 + (lane >> 2) + 8][h] = ss1;
    }
    __syncthreads();

    int r0o = t * 16 + (lane >> 2);
    int r1o = r0o + 8;
    float inv0 = 1.f / fmaxf(sqrtf(sP[r0o][0] + sP[r0o][1]), 1e-12f);
    float inv1 = 1.f / fmaxf(sqrtf(sP[r1o][0] + sP[r1o][1]), 1e-12f);
    int gr0 = rbase + r0o, gr1 = rbase + r1o;
    #pragma unroll
    for (int nt = 0; nt < 4; nt++) {
        int c = h * 32 + nt * 8 + (lane & 3) * 2;
        if (gr0 < N_NODES) {
            float x0 = d1[nt * 4 + 0] * inv0, x1 = d1[nt * 4 + 1] * inv0;
            *(float2*)&out[gr0 * 160 + 64 + c] = make_float2(x0, x1);
            g_egoB[gr0 * 32 + (c >> 1)] = make_float2(x0, x1);
            g_egoBh[gr0 * 32 + (c >> 1)] = __floats2half2_rn(x0, x1);
        }
        if (gr1 < N_NODES) {
            float x0 = d1[nt * 4 + 2] * inv1, x1 = d1[nt * 4 + 3] * inv1;
            *(float2*)&out[gr1 * 160 + 64 + c] = make_float2(x0, x1);
            g_egoB[gr1 * 32 + (c >> 1)] = make_float2(x0, x1);
            g_egoBh[gr1 * 32 + (c >> 1)] = __floats2half2_rn(x0, x1);
        }
    }
}

// ---------------------------------------------------------------------------
// Fused layer 2: same structure, N=32.
// smem: sA 9216 | sM 9216 | union(sE 12288 / sW1 5120 + sW2 5120) | sP 512
// ---------------------------------------------------------------------------
__global__ __launch_bounds__(256, 5) void k_layer2(
    const float* __restrict__ b1, const float* __restrict__ b2,
    float* __restrict__ out)
{
    __shared__ __align__(16) char smem_raw[9216 * 2 + 12288 + 512];
    __half* sA = (__half*)smem_raw;
    __half* sM = (__half*)(smem_raw + 9216);
    int2*   sE = (int2*)(smem_raw + 18432);
    __half* sW1 = (__half*)(smem_raw + 18432);
    __half* sW2 = (__half*)(smem_raw + 18432 + 5120);
    float (*sP)[2] = (float(*)[2])(smem_raw + 18432 + 12288);

    int tid = threadIdx.x;
    int wid = tid >> 5;
    int lane = tid & 31;
    int rbase = blockIdx.x * 64;
    int rend = min(rbase + 64, N_NODES);

    if (rbase + 64 > N_NODES) {
        for (int i = tid; i < 64 * 36; i += 256) {
            ((uint32_t*)sA)[i] = 0;
            ((uint32_t*)sM)[i] = 0;
        }
    }
    int ebase = g_off[rbase];
    int etotal = g_off[rend] - ebase;
    bool use_smem = (etotal <= EDGE_CAP2);
    if (use_smem) {
        for (int i = tid; i < etotal; i += 256)
            sE[i] = g_edges[ebase + i];
    }
    __syncthreads();

    for (int rr = 0; rr < 8; rr += 2) {
        int lrow = wid * 8 + rr;
        int r0 = rbase + lrow;
        if (r0 >= N_NODES) break;
        int r1 = r0 + 1;
        bool v1 = (r1 < N_NODES);
        int s0 = g_off[r0], e0 = g_off[r0 + 1];
        int s1 = v1 ? g_off[r1] : 0, e1 = v1 ? g_off[r1 + 1] : 0;
        float ax0 = 0.f, ay0 = 0.f, ax1 = 0.f, ay1 = 0.f;
        if (use_smem) {
            int rs1 = v1 ? s1 - ebase : 0, re1 = v1 ? e1 - ebase : 0;
            gather_pair(sE, g_egoBh, lane, s0 - ebase, e0 - ebase, rs1, re1,
                        ax0, ay0, ax1, ay1);
        } else {
            gather_pair(g_edges, g_egoBh, lane, s0, e0, s1, e1,
                        ax0, ay0, ax1, ay1);
        }
        float2 eg = g_egoB[r0 * 32 + lane];
        *(__half2*)&sA[lrow * 72 + 2 * lane] = __floats2half2_rn(eg.x + ax0, eg.y + ay0);
        *(__half2*)&sM[lrow * 72 + 2 * lane] = __floats2half2_rn(eg.x * ax0, eg.y * ay0);
        if (v1) {
            float2 eg1 = g_egoB[r1 * 32 + lane];
            *(__half2*)&sA[(lrow + 1) * 72 + 2 * lane] = __floats2half2_rn(eg1.x + ax1, eg1.y + ay1);
            *(__half2*)&sM[(lrow + 1) * 72 + 2 * lane] = __floats2half2_rn(eg1.x * ax1, eg1.y * ay1);
        }
    }
    __syncthreads();

    for (int i = tid; i < 320; i += 256) {
        ((int4*)sW1)[i] = ((const int4*)g_w1hB)[i];
        ((int4*)sW2)[i] = ((const int4*)g_w2hB)[i];
    }
    __syncthreads();

    int t = wid >> 1;
    int h = wid & 1;

    float d1[8], d2[8];
    #pragma unroll
    for (int nt = 0; nt < 2; nt++) {
        int c = h * 16 + nt * 8 + (lane & 3) * 2;
        float bb1a = b1[c], bb1b = b1[c + 1];
        float bb2a = b2[c], bb2b = b2[c + 1];
        d1[nt * 4 + 0] = bb1a; d1[nt * 4 + 1] = bb1b;
        d1[nt * 4 + 2] = bb1a; d1[nt * 4 + 3] = bb1b;
        d2[nt * 4 + 0] = bb2a; d2[nt * 4 + 1] = bb2b;
        d2[nt * 4 + 2] = bb2a; d2[nt * 4 + 3] = bb2b;
    }

    int q = lane >> 3;
    int ri = lane & 7;
    int arow = t * 16 + (q & 1) * 8 + ri;
    int acol = (q >> 1) * 8;
    uint32_t aA = smem_u32(&sA[arow * 72 + acol]);
    uint32_t aM = smem_u32(&sM[arow * 72 + acol]);
    int g2 = q & 1;
    uint32_t bW1 = smem_u32(&sW1[(g2 * 8 + ri) * 40 + h * 16]);
    uint32_t bW2 = smem_u32(&sW2[(g2 * 8 + ri) * 40 + h * 16]);

    #pragma unroll
    for (int ks = 0; ks < 4; ks++) {
        uint32_t a0, a1, a2, a3;
        LDSM_X4(a0, a1, a2, a3, aA + ks * 32);
        #pragma unroll
        for (int nt = 0; nt < 2; nt++) {
            uint32_t b0, b1r;
            LDSM_X2T(b0, b1r, bW1 + ks * 16 * 80 + nt * 16);
            MMA16816(&d1[nt * 4], a0, a1, a2, a3, b0, b1r);
        }
        LDSM_X4(a0, a1, a2, a3, aM + ks * 32);
        #pragma unroll
        for (int nt = 0; nt < 2; nt++) {
            uint32_t b0, b1r;
            LDSM_X2T(b0, b1r, bW2 + ks * 16 * 80 + nt * 16);
            MMA16816(&d2[nt * 4], a0, a1, a2, a3, b0, b1r);
        }
    }

    float ss0 = 0.f, ss1 = 0.f;
    #pragma unroll
    for (int nt = 0; nt < 2; nt++) {
        #pragma unroll
        for (int i = 0; i < 4; i++) {
            float v1 = d1[nt * 4 + i], v2 = d2[nt * 4 + i];
            float v = (v1 > 0.f ? v1 : 0.01f * v1) + (v2 > 0.f ? v2 : 0.01f * v2);
            d1[nt * 4 + i] = v;
            if (i < 2) ss0 += v * v; else ss1 += v * v;
        }
    }
    ss0 += __shfl_xor_sync(0xFFFFFFFFu, ss0, 1);
    ss0 += __shfl_xor_sync(0xFFFFFFFFu, ss0, 2);
    ss1 += __shfl_xor_sync(0xFFFFFFFFu, ss1, 1);
    ss1 += __shfl_xor_sync(0xFFFFFFFFu, ss1, 2);
    if ((lane & 3) == 0) {
        sP[t * 16 + (lane >> 2)][h] = ss0;
        sP[t * 16 + (lane >> 2) + 8][h] = ss1;
    }
    __syncthreads();

    int r0o = t * 16 + (lane >> 2);
    int r1o = r0o + 8;
    float inv0 = 1.f / fmaxf(sqrtf(sP[r0o][0] + sP[r0o][1]), 1e-12f);
    float inv1 = 1.f / fmaxf(sqrtf(sP[r1o][0] + sP[r1o][1]), 1e-12f);
    int gr0 = rbase + r0o, gr1 = rbase + r1o;
    #pragma unroll
    for (int nt = 0; nt < 2; nt++) {
        int c = h * 16 + nt * 8 + (lane & 3) * 2;
        if (gr0 < N_NODES) {
            *(float2*)&out[gr0 * 160 + 128 + c] =
                make_float2(d1[nt * 4 + 0] * inv0, d1[nt * 4 + 1] * inv0);
        }
        if (gr1 < N_NODES) {
            *(float2*)&out[gr1 * 160 + 128 + c] =
                make_float2(d1[nt * 4 + 2] * inv1, d1[nt * 4 + 3] * inv1);
        }
    }
}

// ---------------------------------------------------------------------------
extern "C" void kernel_launch(void* const* d_in, const int* in_sizes, int n_in,
                              void* d_out, int out_size)
{
    const float* user_tab = (const float*)d_in[0];
    const float* entity_tab = (const float*)d_in[1];
    const float* A_vals = (const float*)d_in[2];
    const float* W1_1 = (const float*)d_in[3];
    const float* b1_1 = (const float*)d_in[4];
    const float* W2_1 = (const float*)d_in[5];
    const float* b2_1 = (const float*)d_in[6];
    const float* W1_2 = (const float*)d_in[7];
    const float* b1_2 = (const float*)d_in[8];
    const float* W2_2 = (const float*)d_in[9];
    const float* b2_2 = (const float*)d_in[10];
    const int* A_rows = (const int*)d_in[11];
    const int* A_cols = (const int*)d_in[12];
    float* out = (float*)d_out;

    int eg = (N_EDGES + 255) / 256;

    void* cnt_ptr = nullptr;
    cudaGetSymbolAddress(&cnt_ptr, g_cnt);
    cudaMemsetAsync(cnt_ptr, 0, N_NODES * sizeof(int));
    void* st_ptr = nullptr;
    cudaGetSymbolAddress(&st_ptr, g_state);
    cudaMemsetAsync(st_ptr, 0, SCAN_NB * sizeof(ull));

    // 0: init (ego + out[:,0:64] + histogram + fp16 weight pack)
    k_init<<<(N_NODES * 16 + 255) / 256, 256>>>(
        (const float4*)user_tab, (const float4*)entity_tab, A_rows,
        W1_1, W2_1, W1_2, W2_2, (float4*)out);
    // 1: scan
    k_scan<<<SCAN_NB, SCAN_BS>>>();
    // 2: scatter
    k_scatter<<<eg, 256>>>(A_rows, A_cols, A_vals);
    // 3: fused layer 1 (tensor-core GEMM, staged edges, interleaved gather)
    k_layer1<<<(N_NODES + 63) / 64, 256>>>(b1_1, b2_1, out);
    // 4: fused layer 2
    k_layer2<<<(N_NODES + 63) / 64, 256>>>(b1_2, b2_2, out);
}

// round 15
// speedup vs baseline: 1.1986x; 1.0235x over previous
#include <cuda_runtime.h>
#include <cuda_fp16.h>
#include <cstdint>

#define N_USERS 30000
#define N_NODES 100000
#define N_EDGES 1600000

#define SCAN_BS 512
#define SCAN_NB ((N_NODES + SCAN_BS - 1) / SCAN_BS)   // 196
#define EDGE_CAP1 2304    // layer1 smem edge buffer (aliased with weight tiles)
#define EDGE_CAP2 1536    // layer2

typedef unsigned long long ull;

// Scratch
__device__ float4  g_egoA[N_NODES * 16];     // layer-0 ego fp32
__device__ float2  g_egoB[N_NODES * 32];     // layer-1 ego fp32
__device__ __half2 g_egoAh[N_NODES * 32];    // fp16 shadows (gather only)
__device__ __half2 g_egoBh[N_NODES * 32];
__device__ int  g_cnt[N_NODES];
__device__ int  g_off[N_NODES + 1];
__device__ int  g_cur[N_NODES];
__device__ ull  g_state[SCAN_NB];
__device__ int2 g_edges[N_EDGES];            // row-sorted (col*128 byte-off, half2(v,v) bits)
// pre-converted fp16 weights in padded LDSM layout
__device__ __align__(16) __half g_w1hA[64 * 72];
__device__ __align__(16) __half g_w2hA[64 * 72];
__device__ __align__(16) __half g_w1hB[64 * 40];
__device__ __align__(16) __half g_w2hB[64 * 40];

__device__ __forceinline__ __half2 h2bits(int b) {
    __half2 h; *(int*)&h = b; return h;
}
__device__ __forceinline__ uint32_t smem_u32(const void* p) {
    return (uint32_t)__cvta_generic_to_shared(p);
}
__device__ __forceinline__ __half2 ld_h2(const char* base, int boff) {
    return *(const __half2*)(base + boff);
}

#define LDSM_X4(r0, r1, r2, r3, addr) \
    asm volatile("ldmatrix.sync.aligned.m8n8.x4.shared.b16 {%0,%1,%2,%3}, [%4];" \
        : "=r"(r0), "=r"(r1), "=r"(r2), "=r"(r3) : "r"(addr))
#define LDSM_X2T(r0, r1, addr) \
    asm volatile("ldmatrix.sync.aligned.m8n8.x2.trans.shared.b16 {%0,%1}, [%2];" \
        : "=r"(r0), "=r"(r1) : "r"(addr))
#define MMA16816(d, a0, a1, a2, a3, b0, b1) \
    asm volatile("mma.sync.aligned.m16n8k16.row.col.f32.f16.f16.f32 " \
        "{%0,%1,%2,%3},{%4,%5,%6,%7},{%8,%9},{%0,%1,%2,%3};" \
        : "+f"((d)[0]), "+f"((d)[1]), "+f"((d)[2]), "+f"((d)[3]) \
        : "r"(a0), "r"(a1), "r"(a2), "r"(a3), "r"(b0), "r"(b1))

// ---------------------------------------------------------------------------
// k_init: ego0 (fp32 + fp16 shadow), out[:,0:64], edge histogram, fp16 weights.
// ---------------------------------------------------------------------------
__global__ __launch_bounds__(256) void k_init(
    const float4* __restrict__ user4,
    const float4* __restrict__ ent4,
    const int* __restrict__ rows,
    const float* __restrict__ W1_1, const float* __restrict__ W2_1,
    const float* __restrict__ W1_2, const float* __restrict__ W2_2,
    float4* __restrict__ out4)
{
    int idx = blockIdx.x * blockDim.x + threadIdx.x;
    if (idx < N_EDGES) atomicAdd(&g_cnt[rows[idx]], 1);
    if (idx < 4096) {
        int k = idx >> 6, n = idx & 63;
        g_w1hA[k * 72 + n] = __float2half(W1_1[idx]);
        g_w2hA[k * 72 + n] = __float2half(W2_1[idx]);
    } else if (idx < 4096 + 2048) {
        int t = idx - 4096;
        int k = t >> 5, n = t & 31;
        g_w1hB[k * 40 + n] = __float2half(W1_2[t]);
        g_w2hB[k * 40 + n] = __float2half(W2_2[t]);
    }
    if (idx >= N_NODES * 16) return;
    int row = idx >> 4;
    int part = idx & 15;
    float4 v = (row < N_USERS) ? user4[row * 16 + part]
                               : ent4[(row - N_USERS) * 16 + part];
    g_egoA[idx] = v;
    g_egoAh[row * 32 + 2 * part]     = __floats2half2_rn(v.x, v.y);
    g_egoAh[row * 32 + 2 * part + 1] = __floats2half2_rn(v.z, v.w);
    out4[row * 40 + part] = v;
}

// ---------------------------------------------------------------------------
// Single-pass exclusive scan (decoupled lookback).
// ---------------------------------------------------------------------------
__global__ __launch_bounds__(SCAN_BS) void k_scan()
{
    __shared__ int warp_sums[16];
    __shared__ int blk_prefix;

    int tid = threadIdx.x;
    int bid = blockIdx.x;
    int lane = tid & 31;
    int wid = tid >> 5;
    int i = bid * SCAN_BS + tid;
    int v = (i < N_NODES) ? g_cnt[i] : 0;

    int x = v;
    #pragma unroll
    for (int off = 1; off < 32; off <<= 1) {
        int t = __shfl_up_sync(0xFFFFFFFFu, x, off);
        if (lane >= off) x += t;
    }
    if (lane == 31) warp_sums[wid] = x;
    __syncthreads();
    if (wid == 0) {
        int s = (lane < 16) ? warp_sums[lane] : 0;
        #pragma unroll
        for (int off = 1; off < 16; off <<= 1) {
            int t = __shfl_up_sync(0xFFFFFFFFu, s, off);
            if (lane >= off) s += t;
        }
        if (lane < 16) warp_sums[lane] = s;
    }
    __syncthreads();
    int incl = x + (wid > 0 ? warp_sums[wid - 1] : 0);
    int block_total = warp_sums[15];

    if (tid == 0) {
        if (bid == 0) {
            atomicExch(&g_state[0], (2ULL << 32) | (unsigned)block_total);
            blk_prefix = 0;
        } else {
            atomicExch(&g_state[bid], (1ULL << 32) | (unsigned)block_total);
            int pref = 0;
            int j = bid - 1;
            while (true) {
                ull s = atomicAdd(&g_state[j], 0ULL);
                unsigned st = (unsigned)(s >> 32);
                if (st == 2) { pref += (int)(unsigned)s; break; }
                if (st == 1) { pref += (int)(unsigned)s; j--; }
            }
            atomicExch(&g_state[bid], (2ULL << 32) | (unsigned)(pref + block_total));
            blk_prefix = pref;
        }
    }
    __syncthreads();

    int excl = blk_prefix + incl - v;
    if (i < N_NODES) { g_off[i] = excl; g_cur[i] = excl; }
    if (i == N_NODES - 1) g_off[N_NODES] = N_EDGES;
}

__global__ __launch_bounds__(256) void k_scatter(
    const int* __restrict__ rows,
    const int* __restrict__ cols,
    const float* __restrict__ vals)
{
    int e = blockIdx.x * blockDim.x + threadIdx.x;
    if (e >= N_EDGES) return;
    int pos = atomicAdd(&g_cur[rows[e]], 1);
    float v = vals[e];
    __half2 vv = __floats2half2_rn(v, v);
    g_edges[pos] = make_int2(cols[e] << 7, *(const int*)&vv);   // byte offset
}

// ---------------------------------------------------------------------------
// Tail gather for one row (index already even-aligned). 8-edge groups + scalar.
// base = (const char*)egoH + lane*4; cv.x is a pre-scaled byte offset.
// ---------------------------------------------------------------------------
__device__ __forceinline__ void gather_tail(
    const int2* __restrict__ E, const char* base,
    int i, int e, float& ax, float& ay)
{
    const int4* ep = (const int4*)E;
    for (; i + 7 < e; i += 8) {
        int4 p0 = ep[(i >> 1) + 0];
        int4 p1 = ep[(i >> 1) + 1];
        int4 p2 = ep[(i >> 1) + 2];
        int4 p3 = ep[(i >> 1) + 3];
        __half2 x0 = ld_h2(base, p0.x);
        __half2 x1 = ld_h2(base, p0.z);
        __half2 x2 = ld_h2(base, p1.x);
        __half2 x3 = ld_h2(base, p1.z);
        __half2 x4 = ld_h2(base, p2.x);
        __half2 x5 = ld_h2(base, p2.z);
        __half2 x6 = ld_h2(base, p3.x);
        __half2 x7 = ld_h2(base, p3.z);
        __half2 acc = __hmul2(h2bits(p0.y), x0);
        acc = __hfma2(h2bits(p0.w), x1, acc);
        acc = __hfma2(h2bits(p1.y), x2, acc);
        acc = __hfma2(h2bits(p1.w), x3, acc);
        __half2 acc2 = __hmul2(h2bits(p2.y), x4);
        acc2 = __hfma2(h2bits(p2.w), x5, acc2);
        acc2 = __hfma2(h2bits(p3.y), x6, acc2);
        acc2 = __hfma2(h2bits(p3.w), x7, acc2);
        float2 f = __half22float2(acc);
        ax += f.x; ay += f.y;
        f = __half22float2(acc2);
        ax += f.x; ay += f.y;
    }
    for (; i < e; i++) {
        int2 cv = E[i];
        __half2 p = __hmul2(h2bits(cv.y), ld_h2(base, cv.x));
        float2 f = __half22float2(p);
        ax += f.x; ay += f.y;
    }
}

// ---------------------------------------------------------------------------
// Interleaved 2-row gather: per iteration, 4 descriptors + 8 gather loads
// covering TWO independent accumulation chains (4 edges per row).
// ---------------------------------------------------------------------------
__device__ __forceinline__ void gather_pair(
    const int2* __restrict__ E, const char* base,
    int i0, int e0, int i1, int e1,
    float& ax0, float& ay0, float& ax1, float& ay1)
{
    if (i0 < e0 && (i0 & 1)) {
        int2 cv = E[i0];
        __half2 p = __hmul2(h2bits(cv.y), ld_h2(base, cv.x));
        float2 f = __half22float2(p);
        ax0 += f.x; ay0 += f.y;
        i0++;
    }
    if (i1 < e1 && (i1 & 1)) {
        int2 cv = E[i1];
        __half2 p = __hmul2(h2bits(cv.y), ld_h2(base, cv.x));
        float2 f = __half22float2(p);
        ax1 += f.x; ay1 += f.y;
        i1++;
    }
    const int4* ep = (const int4*)E;
    while (i0 + 3 < e0 && i1 + 3 < e1) {
        int4 c00 = ep[i0 >> 1];
        int4 c01 = ep[(i0 >> 1) + 1];
        int4 c10 = ep[i1 >> 1];
        int4 c11 = ep[(i1 >> 1) + 1];
        __half2 x0 = ld_h2(base, c00.x);
        __half2 x1 = ld_h2(base, c00.z);
        __half2 x2 = ld_h2(base, c01.x);
        __half2 x3 = ld_h2(base, c01.z);
        __half2 y0 = ld_h2(base, c10.x);
        __half2 y1 = ld_h2(base, c10.z);
        __half2 y2 = ld_h2(base, c11.x);
        __half2 y3 = ld_h2(base, c11.z);
        __half2 a = __hmul2(h2bits(c00.y), x0);
        a = __hfma2(h2bits(c00.w), x1, a);
        a = __hfma2(h2bits(c01.y), x2, a);
        a = __hfma2(h2bits(c01.w), x3, a);
        float2 f = __half22float2(a);
        ax0 += f.x; ay0 += f.y;
        __half2 b = __hmul2(h2bits(c10.y), y0);
        b = __hfma2(h2bits(c10.w), y1, b);
        b = __hfma2(h2bits(c11.y), y2, b);
        b = __hfma2(h2bits(c11.w), y3, b);
        f = __half22float2(b);
        ax1 += f.x; ay1 += f.y;
        i0 += 4; i1 += 4;
    }
    gather_tail(E, base, i0, e0, ax0, ay0);
    gather_tail(E, base, i1, e1, ax1, ay1);
}

// ---------------------------------------------------------------------------
// Fused layer 1: edge stage -> interleaved pair gather (8 rows/warp) ->
// [weights overwrite the edge buffer] -> mma.sync GEMMs -> lrelu/sum/l2norm.
// smem: sA 9216 | sM 9216 | union(sE 18432 / sW1 9216 + sW2 9216) | sP 512
// ---------------------------------------------------------------------------
__global__ __launch_bounds__(256, 5) void k_layer1(
    const float* __restrict__ b1, const float* __restrict__ b2,
    float* __restrict__ out)
{
    __shared__ __align__(16) char smem_raw[9216 * 2 + 18432 + 512];
    __half* sA = (__half*)smem_raw;
    __half* sM = (__half*)(smem_raw + 9216);
    int2*   sE = (int2*)(smem_raw + 18432);
    __half* sW1 = (__half*)(smem_raw + 18432);
    __half* sW2 = (__half*)(smem_raw + 18432 + 9216);
    float (*sP)[2] = (float(*)[2])(smem_raw + 36864);

    int tid = threadIdx.x;
    int wid = tid >> 5;
    int lane = tid & 31;
    int rbase = blockIdx.x * 64;
    int rend = min(rbase + 64, N_NODES);

    if (rbase + 64 > N_NODES) {
        for (int i = tid; i < 64 * 36; i += 256) {
            ((uint32_t*)sA)[i] = 0;
            ((uint32_t*)sM)[i] = 0;
        }
    }
    // stage this block's edge window (contiguous, coalesced)
    int ebase = g_off[rbase];
    int etotal = g_off[rend] - ebase;
    bool use_smem = (etotal <= EDGE_CAP1);
    if (use_smem) {
        for (int i = tid; i < etotal; i += 256)
            sE[i] = g_edges[ebase + i];
    }
    __syncthreads();

    // gather phase: warp handles rows [wid*8, wid*8+8), two at a time
    const float2* egoA2 = (const float2*)g_egoA;
    const char* base = (const char*)g_egoAh + lane * 4;
    for (int rr = 0; rr < 8; rr += 2) {
        int lrow = wid * 8 + rr;
        int r0 = rbase + lrow;
        if (r0 >= N_NODES) break;
        int r1 = r0 + 1;
        bool v1 = (r1 < N_NODES);
        int s0 = g_off[r0], e0 = g_off[r0 + 1];
        int s1 = v1 ? g_off[r1] : 0, e1 = v1 ? g_off[r1 + 1] : 0;
        float ax0 = 0.f, ay0 = 0.f, ax1 = 0.f, ay1 = 0.f;
        if (use_smem) {
            int rs1 = v1 ? s1 - ebase : 0, re1 = v1 ? e1 - ebase : 0;
            gather_pair(sE, base, s0 - ebase, e0 - ebase, rs1, re1,
                        ax0, ay0, ax1, ay1);
        } else {
            gather_pair(g_edges, base, s0, e0, s1, e1,
                        ax0, ay0, ax1, ay1);
        }
        float2 eg = egoA2[r0 * 32 + lane];
        *(__half2*)&sA[lrow * 72 + 2 * lane] = __floats2half2_rn(eg.x + ax0, eg.y + ay0);
        *(__half2*)&sM[lrow * 72 + 2 * lane] = __floats2half2_rn(eg.x * ax0, eg.y * ay0);
        if (v1) {
            float2 eg1 = egoA2[r1 * 32 + lane];
            *(__half2*)&sA[(lrow + 1) * 72 + 2 * lane] = __floats2half2_rn(eg1.x + ax1, eg1.y + ay1);
            *(__half2*)&sM[(lrow + 1) * 72 + 2 * lane] = __floats2half2_rn(eg1.x * ax1, eg1.y * ay1);
        }
    }
    __syncthreads();

    // weights overwrite the (dead) edge buffer: plain int4 copy of packed fp16
    for (int i = tid; i < 576; i += 256) {
        ((int4*)sW1)[i] = ((const int4*)g_w1hA)[i];
        ((int4*)sW2)[i] = ((const int4*)g_w2hA)[i];
    }
    __syncthreads();

    // mma phase
    int t = wid >> 1;
    int h = wid & 1;

    float d1[16], d2[16];
    #pragma unroll
    for (int nt = 0; nt < 4; nt++) {
        int c = h * 32 + nt * 8 + (lane & 3) * 2;
        float bb1a = b1[c], bb1b = b1[c + 1];
        float bb2a = b2[c], bb2b = b2[c + 1];
        d1[nt * 4 + 0] = bb1a; d1[nt * 4 + 1] = bb1b;
        d1[nt * 4 + 2] = bb1a; d1[nt * 4 + 3] = bb1b;
        d2[nt * 4 + 0] = bb2a; d2[nt * 4 + 1] = bb2b;
        d2[nt * 4 + 2] = bb2a; d2[nt * 4 + 3] = bb2b;
    }

    int q = lane >> 3;
    int ri = lane & 7;
    int arow = t * 16 + (q & 1) * 8 + ri;
    int acol = (q >> 1) * 8;
    uint32_t aA = smem_u32(&sA[arow * 72 + acol]);
    uint32_t aM = smem_u32(&sM[arow * 72 + acol]);
    int g2 = q & 1;
    uint32_t bW1 = smem_u32(&sW1[(g2 * 8 + ri) * 72 + h * 32]);
    uint32_t bW2 = smem_u32(&sW2[(g2 * 8 + ri) * 72 + h * 32]);

    #pragma unroll
    for (int ks = 0; ks < 4; ks++) {
        uint32_t a0, a1, a2, a3;
        LDSM_X4(a0, a1, a2, a3, aA + ks * 32);
        #pragma unroll
        for (int nt = 0; nt < 4; nt++) {
            uint32_t b0, b1r;
            LDSM_X2T(b0, b1r, bW1 + ks * 16 * 144 + nt * 16);
            MMA16816(&d1[nt * 4], a0, a1, a2, a3, b0, b1r);
        }
        LDSM_X4(a0, a1, a2, a3, aM + ks * 32);
        #pragma unroll
        for (int nt = 0; nt < 4; nt++) {
            uint32_t b0, b1r;
            LDSM_X2T(b0, b1r, bW2 + ks * 16 * 144 + nt * 16);
            MMA16816(&d2[nt * 4], a0, a1, a2, a3, b0, b1r);
        }
    }

    // epilogue
    float ss0 = 0.f, ss1 = 0.f;
    #pragma unroll
    for (int nt = 0; nt < 4; nt++) {
        #pragma unroll
        for (int i = 0; i < 4; i++) {
            float v1 = d1[nt * 4 + i], v2 = d2[nt * 4 + i];
            float v = (v1 > 0.f ? v1 : 0.01f * v1) + (v2 > 0.f ? v2 : 0.01f * v2);
            d1[nt * 4 + i] = v;
            if (i < 2) ss0 += v * v; else ss1 += v * v;
        }
    }
    ss0 += __shfl_xor_sync(0xFFFFFFFFu, ss0, 1);
    ss0 += __shfl_xor_sync(0xFFFFFFFFu, ss0, 2);
    ss1 += __shfl_xor_sync(0xFFFFFFFFu, ss1, 1);
    ss1 += __shfl_xor_sync(0xFFFFFFFFu, ss1, 2);
    if ((lane & 3) == 0) {
        sP[t * 16 + (lane >> 2)][h] = ss0;
        sP[t * 16 + (lane >> 2) + 8][h] = ss1;
    }
    __syncthreads();

    int r0o = t * 16 + (lane >> 2);
    int r1o = r0o + 8;
    float inv0 = 1.f / fmaxf(sqrtf(sP[r0o][0] + sP[r0o][1]), 1e-12f);
    float inv1 = 1.f / fmaxf(sqrtf(sP[r1o][0] + sP[r1o][1]), 1e-12f);
    int gr0 = rbase + r0o, gr1 = rbase + r1o;
    #pragma unroll
    for (int nt = 0; nt < 4; nt++) {
        int c = h * 32 + nt * 8 + (lane & 3) * 2;
        if (gr0 < N_NODES) {
            float x0 = d1[nt * 4 + 0] * inv0, x1 = d1[nt * 4 + 1] * inv0;
            *(float2*)&out[gr0 * 160 + 64 + c] = make_float2(x0, x1);
            g_egoB[gr0 * 32 + (c >> 1)] = make_float2(x0, x1);
            g_egoBh[gr0 * 32 + (c >> 1)] = __floats2half2_rn(x0, x1);
        }
        if (gr1 < N_NODES) {
            float x0 = d1[nt * 4 + 2] * inv1, x1 = d1[nt * 4 + 3] * inv1;
            *(float2*)&out[gr1 * 160 + 64 + c] = make_float2(x0, x1);
            g_egoB[gr1 * 32 + (c >> 1)] = make_float2(x0, x1);
            g_egoBh[gr1 * 32 + (c >> 1)] = __floats2half2_rn(x0, x1);
        }
    }
}

// ---------------------------------------------------------------------------
// Fused layer 2: same structure, N=32.
// smem: sA 9216 | sM 9216 | union(sE 12288 / sW1 5120 + sW2 5120) | sP 512
// ---------------------------------------------------------------------------
__global__ __launch_bounds__(256, 5) void k_layer2(
    const float* __restrict__ b1, const float* __restrict__ b2,
    float* __restrict__ out)
{
    __shared__ __align__(16) char smem_raw[9216 * 2 + 12288 + 512];
    __half* sA = (__half*)smem_raw;
    __half* sM = (__half*)(smem_raw + 9216);
    int2*   sE = (int2*)(smem_raw + 18432);
    __half* sW1 = (__half*)(smem_raw + 18432);
    __half* sW2 = (__half*)(smem_raw + 18432 + 5120);
    float (*sP)[2] = (float(*)[2])(smem_raw + 18432 + 12288);

    int tid = threadIdx.x;
    int wid = tid >> 5;
    int lane = tid & 31;
    int rbase = blockIdx.x * 64;
    int rend = min(rbase + 64, N_NODES);

    if (rbase + 64 > N_NODES) {
        for (int i = tid; i < 64 * 36; i += 256) {
            ((uint32_t*)sA)[i] = 0;
            ((uint32_t*)sM)[i] = 0;
        }
    }
    int ebase = g_off[rbase];
    int etotal = g_off[rend] - ebase;
    bool use_smem = (etotal <= EDGE_CAP2);
    if (use_smem) {
        for (int i = tid; i < etotal; i += 256)
            sE[i] = g_edges[ebase + i];
    }
    __syncthreads();

    const char* base = (const char*)g_egoBh + lane * 4;
    for (int rr = 0; rr < 8; rr += 2) {
        int lrow = wid * 8 + rr;
        int r0 = rbase + lrow;
        if (r0 >= N_NODES) break;
        int r1 = r0 + 1;
        bool v1 = (r1 < N_NODES);
        int s0 = g_off[r0], e0 = g_off[r0 + 1];
        int s1 = v1 ? g_off[r1] : 0, e1 = v1 ? g_off[r1 + 1] : 0;
        float ax0 = 0.f, ay0 = 0.f, ax1 = 0.f, ay1 = 0.f;
        if (use_smem) {
            int rs1 = v1 ? s1 - ebase : 0, re1 = v1 ? e1 - ebase : 0;
            gather_pair(sE, base, s0 - ebase, e0 - ebase, rs1, re1,
                        ax0, ay0, ax1, ay1);
        } else {
            gather_pair(g_edges, base, s0, e0, s1, e1,
                        ax0, ay0, ax1, ay1);
        }
        float2 eg = g_egoB[r0 * 32 + lane];
        *(__half2*)&sA[lrow * 72 + 2 * lane] = __floats2half2_rn(eg.x + ax0, eg.y + ay0);
        *(__half2*)&sM[lrow * 72 + 2 * lane] = __floats2half2_rn(eg.x * ax0, eg.y * ay0);
        if (v1) {
            float2 eg1 = g_egoB[r1 * 32 + lane];
            *(__half2*)&sA[(lrow + 1) * 72 + 2 * lane] = __floats2half2_rn(eg1.x + ax1, eg1.y + ay1);
            *(__half2*)&sM[(lrow + 1) * 72 + 2 * lane] = __floats2half2_rn(eg1.x * ax1, eg1.y * ay1);
        }
    }
    __syncthreads();

    for (int i = tid; i < 320; i += 256) {
        ((int4*)sW1)[i] = ((const int4*)g_w1hB)[i];
        ((int4*)sW2)[i] = ((const int4*)g_w2hB)[i];
    }
    __syncthreads();

    int t = wid >> 1;
    int h = wid & 1;

    float d1[8], d2[8];
    #pragma unroll
    for (int nt = 0; nt < 2; nt++) {
        int c = h * 16 + nt * 8 + (lane & 3) * 2;
        float bb1a = b1[c], bb1b = b1[c + 1];
        float bb2a = b2[c], bb2b = b2[c + 1];
        d1[nt * 4 + 0] = bb1a; d1[nt * 4 + 1] = bb1b;
        d1[nt * 4 + 2] = bb1a; d1[nt * 4 + 3] = bb1b;
        d2[nt * 4 + 0] = bb2a; d2[nt * 4 + 1] = bb2b;
        d2[nt * 4 + 2] = bb2a; d2[nt * 4 + 3] = bb2b;
    }

    int q = lane >> 3;
    int ri = lane & 7;
    int arow = t * 16 + (q & 1) * 8 + ri;
    int acol = (q >> 1) * 8;
    uint32_t aA = smem_u32(&sA[arow * 72 + acol]);
    uint32_t aM = smem_u32(&sM[arow * 72 + acol]);
    int g2 = q & 1;
    uint32_t bW1 = smem_u32(&sW1[(g2 * 8 + ri) * 40 + h * 16]);
    uint32_t bW2 = smem_u32(&sW2[(g2 * 8 + ri) * 40 + h * 16]);

    #pragma unroll
    for (int ks = 0; ks < 4; ks++) {
        uint32_t a0, a1, a2, a3;
        LDSM_X4(a0, a1, a2, a3, aA + ks * 32);
        #pragma unroll
        for (int nt = 0; nt < 2; nt++) {
            uint32_t b0, b1r;
            LDSM_X2T(b0, b1r, bW1 + ks * 16 * 80 + nt * 16);
            MMA16816(&d1[nt * 4], a0, a1, a2, a3, b0, b1r);
        }
        LDSM_X4(a0, a1, a2, a3, aM + ks * 32);
        #pragma unroll
        for (int nt = 0; nt < 2; nt++) {
            uint32_t b0, b1r;
            LDSM_X2T(b0, b1r, bW2 + ks * 16 * 80 + nt * 16);
            MMA16816(&d2[nt * 4], a0, a1, a2, a3, b0, b1r);
        }
    }

    float ss0 = 0.f, ss1 = 0.f;
    #pragma unroll
    for (int nt = 0; nt < 2; nt++) {
        #pragma unroll
        for (int i = 0; i < 4; i++) {
            float v1 = d1[nt * 4 + i], v2 = d2[nt * 4 + i];
            float v = (v1 > 0.f ? v1 : 0.01f * v1) + (v2 > 0.f ? v2 : 0.01f * v2);
            d1[nt * 4 + i] = v;
            if (i < 2) ss0 += v * v; else ss1 += v * v;
        }
    }
    ss0 += __shfl_xor_sync(0xFFFFFFFFu, ss0, 1);
    ss0 += __shfl_xor_sync(0xFFFFFFFFu, ss0, 2);
    ss1 += __shfl_xor_sync(0xFFFFFFFFu, ss1, 1);
    ss1 += __shfl_xor_sync(0xFFFFFFFFu, ss1, 2);
    if ((lane & 3) == 0) {
        sP[t * 16 + (lane >> 2)][h] = ss0;
        sP[t * 16 + (lane >> 2) + 8][h] = ss1;
    }
    __syncthreads();

    int r0o = t * 16 + (lane >> 2);
    int r1o = r0o + 8;
    float inv0 = 1.f / fmaxf(sqrtf(sP[r0o][0] + sP[r0o][1]), 1e-12f);
    float inv1 = 1.f / fmaxf(sqrtf(sP[r1o][0] + sP[r1o][1]), 1e-12f);
    int gr0 = rbase + r0o, gr1 = rbase + r1o;
    #pragma unroll
    for (int nt = 0; nt < 2; nt++) {
        int c = h * 16 + nt * 8 + (lane & 3) * 2;
        if (gr0 < N_NODES) {
            *(float2*)&out[gr0 * 160 + 128 + c] =
                make_float2(d1[nt * 4 + 0] * inv0, d1[nt * 4 + 1] * inv0);
        }
        if (gr1 < N_NODES) {
            *(float2*)&out[gr1 * 160 + 128 + c] =
                make_float2(d1[nt * 4 + 2] * inv1, d1[nt * 4 + 3] * inv1);
        }
    }
}

// ---------------------------------------------------------------------------
extern "C" void kernel_launch(void* const* d_in, const int* in_sizes, int n_in,
                              void* d_out, int out_size)
{
    const float* user_tab = (const float*)d_in[0];
    const float* entity_tab = (const float*)d_in[1];
    const float* A_vals = (const float*)d_in[2];
    const float* W1_1 = (const float*)d_in[3];
    const float* b1_1 = (const float*)d_in[4];
    const float* W2_1 = (const float*)d_in[5];
    const float* b2_1 = (const float*)d_in[6];
    const float* W1_2 = (const float*)d_in[7];
    const float* b1_2 = (const float*)d_in[8];
    const float* W2_2 = (const float*)d_in[9];
    const float* b2_2 = (const float*)d_in[10];
    const int* A_rows = (const int*)d_in[11];
    const int* A_cols = (const int*)d_in[12];
    float* out = (float*)d_out;

    int eg = (N_EDGES + 255) / 256;

    void* cnt_ptr = nullptr;
    cudaGetSymbolAddress(&cnt_ptr, g_cnt);
    cudaMemsetAsync(cnt_ptr, 0, N_NODES * sizeof(int));
    void* st_ptr = nullptr;
    cudaGetSymbolAddress(&st_ptr, g_state);
    cudaMemsetAsync(st_ptr, 0, SCAN_NB * sizeof(ull));

    // 0: init (ego + out[:,0:64] + histogram + fp16 weight pack)
    k_init<<<(N_NODES * 16 + 255) / 256, 256>>>(
        (const float4*)user_tab, (const float4*)entity_tab, A_rows,
        W1_1, W2_1, W1_2, W2_2, (float4*)out);
    // 1: scan
    k_scan<<<SCAN_NB, SCAN_BS>>>();
    // 2: scatter (columns stored as pre-scaled byte offsets)
    k_scatter<<<eg, 256>>>(A_rows, A_cols, A_vals);
    // 3: fused layer 1 (tensor-core GEMM, staged edges, interleaved gather)
    k_layer1<<<(N_NODES + 63) / 64, 256>>>(b1_1, b2_1, out);
    // 4: fused layer 2
    k_layer2<<<(N_NODES + 63) / 64, 256>>>(b1_2, b2_2, out);
}

// round 17
// speedup vs baseline: 1.2735x; 1.0625x over previous
#include <cuda_runtime.h>
#include <cuda_fp16.h>
#include <cstdint>

#define N_USERS 30000
#define N_NODES 100000
#define N_EDGES 1600000

#define SCAN_BS 512
#define SCAN_NB ((N_NODES + SCAN_BS - 1) / SCAN_BS)   // 196
#define EDGE_CAP1 2304    // layer1 smem edge buffer (aliased with weight tiles)
#define EDGE_CAP2 1536    // layer2

typedef unsigned long long ull;

// Scratch (ego fp32 lives in `out` itself; only fp16 shadows are kept)
__device__ __half2 g_egoAh[N_NODES * 32];    // fp16 shadows (gather only)
__device__ __half2 g_egoBh[N_NODES * 32];
__device__ int  g_cnt[N_NODES];
__device__ int  g_off[N_NODES + 1];
__device__ int  g_cur[N_NODES];
__device__ ull  g_state[SCAN_NB];
__device__ int2 g_edges[N_EDGES];            // row-sorted (col*128 byte-off, half2(v,v) bits)
// pre-converted fp16 weights in padded LDSM layout
__device__ __align__(16) __half g_w1hA[64 * 72];
__device__ __align__(16) __half g_w2hA[64 * 72];
__device__ __align__(16) __half g_w1hB[64 * 40];
__device__ __align__(16) __half g_w2hB[64 * 40];

__device__ __forceinline__ __half2 h2bits(int b) {
    __half2 h; *(int*)&h = b; return h;
}
__device__ __forceinline__ uint32_t smem_u32(const void* p) {
    return (uint32_t)__cvta_generic_to_shared(p);
}
__device__ __forceinline__ __half2 ld_h2(const char* base, int boff) {
    return *(const __half2*)(base + boff);
}

#define LDSM_X4(r0, r1, r2, r3, addr) \
    asm volatile("ldmatrix.sync.aligned.m8n8.x4.shared.b16 {%0,%1,%2,%3}, [%4];" \
        : "=r"(r0), "=r"(r1), "=r"(r2), "=r"(r3) : "r"(addr))
#define LDSM_X2T(r0, r1, addr) \
    asm volatile("ldmatrix.sync.aligned.m8n8.x2.trans.shared.b16 {%0,%1}, [%2];" \
        : "=r"(r0), "=r"(r1) : "r"(addr))
#define MMA16816(d, a0, a1, a2, a3, b0, b1) \
    asm volatile("mma.sync.aligned.m16n8k16.row.col.f32.f16.f16.f32 " \
        "{%0,%1,%2,%3},{%4,%5,%6,%7},{%8,%9},{%0,%1,%2,%3};" \
        : "+f"((d)[0]), "+f"((d)[1]), "+f"((d)[2]), "+f"((d)[3]) \
        : "r"(a0), "r"(a1), "r"(a2), "r"(a3), "r"(b0), "r"(b1))

// ---------------------------------------------------------------------------
// k_init: ego0 -> out[:,0:64] + fp16 shadow, edge histogram, fp16 weights.
// ---------------------------------------------------------------------------
__global__ __launch_bounds__(256) void k_init(
    const float4* __restrict__ user4,
    const float4* __restrict__ ent4,
    const int* __restrict__ rows,
    const float* __restrict__ W1_1, const float* __restrict__ W2_1,
    const float* __restrict__ W1_2, const float* __restrict__ W2_2,
    float4* __restrict__ out4)
{
    int idx = blockIdx.x * blockDim.x + threadIdx.x;
    if (idx < N_EDGES) atomicAdd(&g_cnt[rows[idx]], 1);
    if (idx < 4096) {
        int k = idx >> 6, n = idx & 63;
        g_w1hA[k * 72 + n] = __float2half(W1_1[idx]);
        g_w2hA[k * 72 + n] = __float2half(W2_1[idx]);
    } else if (idx < 4096 + 2048) {
        int t = idx - 4096;
        int k = t >> 5, n = t & 31;
        g_w1hB[k * 40 + n] = __float2half(W1_2[t]);
        g_w2hB[k * 40 + n] = __float2half(W2_2[t]);
    }
    if (idx >= N_NODES * 16) return;
    int row = idx >> 4;
    int part = idx & 15;
    float4 v = (row < N_USERS) ? user4[row * 16 + part]
                               : ent4[(row - N_USERS) * 16 + part];
    g_egoAh[row * 32 + 2 * part]     = __floats2half2_rn(v.x, v.y);
    g_egoAh[row * 32 + 2 * part + 1] = __floats2half2_rn(v.z, v.w);
    out4[row * 40 + part] = v;
}

// ---------------------------------------------------------------------------
// Single-pass exclusive scan (decoupled lookback).
// ---------------------------------------------------------------------------
__global__ __launch_bounds__(SCAN_BS) void k_scan()
{
    __shared__ int warp_sums[16];
    __shared__ int blk_prefix;

    int tid = threadIdx.x;
    int bid = blockIdx.x;
    int lane = tid & 31;
    int wid = tid >> 5;
    int i = bid * SCAN_BS + tid;
    int v = (i < N_NODES) ? g_cnt[i] : 0;

    int x = v;
    #pragma unroll
    for (int off = 1; off < 32; off <<= 1) {
        int t = __shfl_up_sync(0xFFFFFFFFu, x, off);
        if (lane >= off) x += t;
    }
    if (lane == 31) warp_sums[wid] = x;
    __syncthreads();
    if (wid == 0) {
        int s = (lane < 16) ? warp_sums[lane] : 0;
        #pragma unroll
        for (int off = 1; off < 16; off <<= 1) {
            int t = __shfl_up_sync(0xFFFFFFFFu, s, off);
            if (lane >= off) s += t;
        }
        if (lane < 16) warp_sums[lane] = s;
    }
    __syncthreads();
    int incl = x + (wid > 0 ? warp_sums[wid - 1] : 0);
    int block_total = warp_sums[15];

    if (tid == 0) {
        if (bid == 0) {
            atomicExch(&g_state[0], (2ULL << 32) | (unsigned)block_total);
            blk_prefix = 0;
        } else {
            atomicExch(&g_state[bid], (1ULL << 32) | (unsigned)block_total);
            int pref = 0;
            int j = bid - 1;
            while (true) {
                ull s = atomicAdd(&g_state[j], 0ULL);
                unsigned st = (unsigned)(s >> 32);
                if (st == 2) { pref += (int)(unsigned)s; break; }
                if (st == 1) { pref += (int)(unsigned)s; j--; }
            }
            atomicExch(&g_state[bid], (2ULL << 32) | (unsigned)(pref + block_total));
            blk_prefix = pref;
        }
    }
    __syncthreads();

    int excl = blk_prefix + incl - v;
    if (i < N_NODES) { g_off[i] = excl; g_cur[i] = excl; }
    if (i == N_NODES - 1) g_off[N_NODES] = N_EDGES;
}

__global__ __launch_bounds__(256) void k_scatter(
    const int* __restrict__ rows,
    const int* __restrict__ cols,
    const float* __restrict__ vals)
{
    int e = blockIdx.x * blockDim.x + threadIdx.x;
    if (e >= N_EDGES) return;
    int pos = atomicAdd(&g_cur[rows[e]], 1);
    float v = vals[e];
    __half2 vv = __floats2half2_rn(v, v);
    g_edges[pos] = make_int2(cols[e] << 7, *(const int*)&vv);   // byte offset
}

// ---------------------------------------------------------------------------
// Tail gather for one row (index already even-aligned). 8-edge groups + scalar.
// ---------------------------------------------------------------------------
__device__ __forceinline__ void gather_tail(
    const int2* __restrict__ E, const char* base,
    int i, int e, float& ax, float& ay)
{
    const int4* ep = (const int4*)E;
    for (; i + 7 < e; i += 8) {
        int4 p0 = ep[(i >> 1) + 0];
        int4 p1 = ep[(i >> 1) + 1];
        int4 p2 = ep[(i >> 1) + 2];
        int4 p3 = ep[(i >> 1) + 3];
        __half2 x0 = ld_h2(base, p0.x);
        __half2 x1 = ld_h2(base, p0.z);
        __half2 x2 = ld_h2(base, p1.x);
        __half2 x3 = ld_h2(base, p1.z);
        __half2 x4 = ld_h2(base, p2.x);
        __half2 x5 = ld_h2(base, p2.z);
        __half2 x6 = ld_h2(base, p3.x);
        __half2 x7 = ld_h2(base, p3.z);
        __half2 acc = __hmul2(h2bits(p0.y), x0);
        acc = __hfma2(h2bits(p0.w), x1, acc);
        acc = __hfma2(h2bits(p1.y), x2, acc);
        acc = __hfma2(h2bits(p1.w), x3, acc);
        __half2 acc2 = __hmul2(h2bits(p2.y), x4);
        acc2 = __hfma2(h2bits(p2.w), x5, acc2);
        acc2 = __hfma2(h2bits(p3.y), x6, acc2);
        acc2 = __hfma2(h2bits(p3.w), x7, acc2);
        float2 f = __half22float2(acc);
        ax += f.x; ay += f.y;
        f = __half22float2(acc2);
        ax += f.x; ay += f.y;
    }
    for (; i < e; i++) {
        int2 cv = E[i];
        __half2 p = __hmul2(h2bits(cv.y), ld_h2(base, cv.x));
        float2 f = __half22float2(p);
        ax += f.x; ay += f.y;
    }
}

// ---------------------------------------------------------------------------
// Interleaved 2-row gather (two independent accumulation chains).
// ---------------------------------------------------------------------------
__device__ __forceinline__ void gather_pair(
    const int2* __restrict__ E, const char* base,
    int i0, int e0, int i1, int e1,
    float& ax0, float& ay0, float& ax1, float& ay1)
{
    if (i0 < e0 && (i0 & 1)) {
        int2 cv = E[i0];
        __half2 p = __hmul2(h2bits(cv.y), ld_h2(base, cv.x));
        float2 f = __half22float2(p);
        ax0 += f.x; ay0 += f.y;
        i0++;
    }
    if (i1 < e1 && (i1 & 1)) {
        int2 cv = E[i1];
        __half2 p = __hmul2(h2bits(cv.y), ld_h2(base, cv.x));
        float2 f = __half22float2(p);
        ax1 += f.x; ay1 += f.y;
        i1++;
    }
    const int4* ep = (const int4*)E;
    while (i0 + 3 < e0 && i1 + 3 < e1) {
        int4 c00 = ep[i0 >> 1];
        int4 c01 = ep[(i0 >> 1) + 1];
        int4 c10 = ep[i1 >> 1];
        int4 c11 = ep[(i1 >> 1) + 1];
        __half2 x0 = ld_h2(base, c00.x);
        __half2 x1 = ld_h2(base, c00.z);
        __half2 x2 = ld_h2(base, c01.x);
        __half2 x3 = ld_h2(base, c01.z);
        __half2 y0 = ld_h2(base, c10.x);
        __half2 y1 = ld_h2(base, c10.z);
        __half2 y2 = ld_h2(base, c11.x);
        __half2 y3 = ld_h2(base, c11.z);
        __half2 a = __hmul2(h2bits(c00.y), x0);
        a = __hfma2(h2bits(c00.w), x1, a);
        a = __hfma2(h2bits(c01.y), x2, a);
        a = __hfma2(h2bits(c01.w), x3, a);
        float2 f = __half22float2(a);
        ax0 += f.x; ay0 += f.y;
        __half2 b = __hmul2(h2bits(c10.y), y0);
        b = __hfma2(h2bits(c10.w), y1, b);
        b = __hfma2(h2bits(c11.y), y2, b);
        b = __hfma2(h2bits(c11.w), y3, b);
        f = __half22float2(b);
        ax1 += f.x; ay1 += f.y;
        i0 += 4; i1 += 4;
    }
    gather_tail(E, base, i0, e0, ax0, ay0);
    gather_tail(E, base, i1, e1, ax1, ay1);
}

// ---------------------------------------------------------------------------
// Fused layer 1: edge stage -> interleaved pair gather (8 rows/warp, ego read
// from out[:,0:64]) -> [weights overwrite edge buffer] -> mma.sync GEMMs ->
// lrelu/sum/l2norm -> out[:,64:128] + fp16 shadow.
// smem: sA 9216 | sM 9216 | union(sE 18432 / sW1 9216 + sW2 9216) | sP 512
// ---------------------------------------------------------------------------
__global__ __launch_bounds__(256, 5) void k_layer1(
    const float* __restrict__ b1, const float* __restrict__ b2,
    float* out)
{
    __shared__ __align__(16) char smem_raw[9216 * 2 + 18432 + 512];
    __half* sA = (__half*)smem_raw;
    __half* sM = (__half*)(smem_raw + 9216);
    int2*   sE = (int2*)(smem_raw + 18432);
    __half* sW1 = (__half*)(smem_raw + 18432);
    __half* sW2 = (__half*)(smem_raw + 18432 + 9216);
    float (*sP)[2] = (float(*)[2])(smem_raw + 36864);

    int tid = threadIdx.x;
    int wid = tid >> 5;
    int lane = tid & 31;
    int rbase = blockIdx.x * 64;
    int rend = min(rbase + 64, N_NODES);

    if (rbase + 64 > N_NODES) {
        for (int i = tid; i < 64 * 36; i += 256) {
            ((uint32_t*)sA)[i] = 0;
            ((uint32_t*)sM)[i] = 0;
        }
    }
    // stage this block's edge window (contiguous, coalesced)
    int ebase = g_off[rbase];
    int etotal = g_off[rend] - ebase;
    bool use_smem = (etotal <= EDGE_CAP1);
    if (use_smem) {
        for (int i = tid; i < etotal; i += 256)
            sE[i] = g_edges[ebase + i];
    }
    __syncthreads();

    // gather phase: warp handles rows [wid*8, wid*8+8), two at a time
    const float2* out2 = (const float2*)out;     // ego0 = out[:,0:64]
    const char* base = (const char*)g_egoAh + lane * 4;
    for (int rr = 0; rr < 8; rr += 2) {
        int lrow = wid * 8 + rr;
        int r0 = rbase + lrow;
        if (r0 >= N_NODES) break;
        int r1 = r0 + 1;
        bool v1 = (r1 < N_NODES);
        int s0 = g_off[r0], e0 = g_off[r0 + 1];
        int s1 = v1 ? g_off[r1] : 0, e1 = v1 ? g_off[r1 + 1] : 0;
        float ax0 = 0.f, ay0 = 0.f, ax1 = 0.f, ay1 = 0.f;
        if (use_smem) {
            int rs1 = v1 ? s1 - ebase : 0, re1 = v1 ? e1 - ebase : 0;
            gather_pair(sE, base, s0 - ebase, e0 - ebase, rs1, re1,
                        ax0, ay0, ax1, ay1);
        } else {
            gather_pair(g_edges, base, s0, e0, s1, e1,
                        ax0, ay0, ax1, ay1);
        }
        float2 eg = out2[r0 * 80 + lane];
        *(__half2*)&sA[lrow * 72 + 2 * lane] = __floats2half2_rn(eg.x + ax0, eg.y + ay0);
        *(__half2*)&sM[lrow * 72 + 2 * lane] = __floats2half2_rn(eg.x * ax0, eg.y * ay0);
        if (v1) {
            float2 eg1 = out2[r1 * 80 + lane];
            *(__half2*)&sA[(lrow + 1) * 72 + 2 * lane] = __floats2half2_rn(eg1.x + ax1, eg1.y + ay1);
            *(__half2*)&sM[(lrow + 1) * 72 + 2 * lane] = __floats2half2_rn(eg1.x * ax1, eg1.y * ay1);
        }
    }
    __syncthreads();

    // weights overwrite the (dead) edge buffer: plain int4 copy of packed fp16
    for (int i = tid; i < 576; i += 256) {
        ((int4*)sW1)[i] = ((const int4*)g_w1hA)[i];
        ((int4*)sW2)[i] = ((const int4*)g_w2hA)[i];
    }
    __syncthreads();

    // mma phase
    int t = wid >> 1;
    int h = wid & 1;

    float d1[16], d2[16];
    #pragma unroll
    for (int nt = 0; nt < 4; nt++) {
        int c = h * 32 + nt * 8 + (lane & 3) * 2;
        float bb1a = b1[c], bb1b = b1[c + 1];
        float bb2a = b2[c], bb2b = b2[c + 1];
        d1[nt * 4 + 0] = bb1a; d1[nt * 4 + 1] = bb1b;
        d1[nt * 4 + 2] = bb1a; d1[nt * 4 + 3] = bb1b;
        d2[nt * 4 + 0] = bb2a; d2[nt * 4 + 1] = bb2b;
        d2[nt * 4 + 2] = bb2a; d2[nt * 4 + 3] = bb2b;
    }

    int q = lane >> 3;
    int ri = lane & 7;
    int arow = t * 16 + (q & 1) * 8 + ri;
    int acol = (q >> 1) * 8;
    uint32_t aA = smem_u32(&sA[arow * 72 + acol]);
    uint32_t aM = smem_u32(&sM[arow * 72 + acol]);
    int g2 = q & 1;
    uint32_t bW1 = smem_u32(&sW1[(g2 * 8 + ri) * 72 + h * 32]);
    uint32_t bW2 = smem_u32(&sW2[(g2 * 8 + ri) * 72 + h * 32]);

    #pragma unroll
    for (int ks = 0; ks < 4; ks++) {
        uint32_t a0, a1, a2, a3;
        LDSM_X4(a0, a1, a2, a3, aA + ks * 32);
        #pragma unroll
        for (int nt = 0; nt < 4; nt++) {
            uint32_t b0, b1r;
            LDSM_X2T(b0, b1r, bW1 + ks * 16 * 144 + nt * 16);
            MMA16816(&d1[nt * 4], a0, a1, a2, a3, b0, b1r);
        }
        LDSM_X4(a0, a1, a2, a3, aM + ks * 32);
        #pragma unroll
        for (int nt = 0; nt < 4; nt++) {
            uint32_t b0, b1r;
            LDSM_X2T(b0, b1r, bW2 + ks * 16 * 144 + nt * 16);
            MMA16816(&d2[nt * 4], a0, a1, a2, a3, b0, b1r);
        }
    }

    // epilogue
    float ss0 = 0.f, ss1 = 0.f;
    #pragma unroll
    for (int nt = 0; nt < 4; nt++) {
        #pragma unroll
        for (int i = 0; i < 4; i++) {
            float v1 = d1[nt * 4 + i], v2 = d2[nt * 4 + i];
            float v = (v1 > 0.f ? v1 : 0.01f * v1) + (v2 > 0.f ? v2 : 0.01f * v2);
            d1[nt * 4 + i] = v;
            if (i < 2) ss0 += v * v; else ss1 += v * v;
        }
    }
    ss0 += __shfl_xor_sync(0xFFFFFFFFu, ss0, 1);
    ss0 += __shfl_xor_sync(0xFFFFFFFFu, ss0, 2);
    ss1 += __shfl_xor_sync(0xFFFFFFFFu, ss1, 1);
    ss1 += __shfl_xor_sync(0xFFFFFFFFu, ss1, 2);
    if ((lane & 3) == 0) {
        sP[t * 16 + (lane >> 2)][h] = ss0;
        sP[t * 16 + (lane >> 2) + 8][h] = ss1;
    }
    __syncthreads();

    int r0o = t * 16 + (lane >> 2);
    int r1o = r0o + 8;
    float inv0 = 1.f / fmaxf(sqrtf(sP[r0o][0] + sP[r0o][1]), 1e-12f);
    float inv1 = 1.f / fmaxf(sqrtf(sP[r1o][0] + sP[r1o][1]), 1e-12f);
    int gr0 = rbase + r0o, gr1 = rbase + r1o;
    #pragma unroll
    for (int nt = 0; nt < 4; nt++) {
        int c = h * 32 + nt * 8 + (lane & 3) * 2;
        if (gr0 < N_NODES) {
            float x0 = d1[nt * 4 + 0] * inv0, x1 = d1[nt * 4 + 1] * inv0;
            *(float2*)&out[gr0 * 160 + 64 + c] = make_float2(x0, x1);
            g_egoBh[gr0 * 32 + (c >> 1)] = __floats2half2_rn(x0, x1);
        }
        if (gr1 < N_NODES) {
            float x0 = d1[nt * 4 + 2] * inv1, x1 = d1[nt * 4 + 3] * inv1;
            *(float2*)&out[gr1 * 160 + 64 + c] = make_float2(x0, x1);
            g_egoBh[gr1 * 32 + (c >> 1)] = __floats2half2_rn(x0, x1);
        }
    }
}

// ---------------------------------------------------------------------------
// Fused layer 2: same structure, N=32; ego1 read from out[:,64:128].
// smem: sA 9216 | sM 9216 | union(sE 12288 / sW1 5120 + sW2 5120) | sP 512
// ---------------------------------------------------------------------------
__global__ __launch_bounds__(256, 5) void k_layer2(
    const float* __restrict__ b1, const float* __restrict__ b2,
    float* out)
{
    __shared__ __align__(16) char smem_raw[9216 * 2 + 12288 + 512];
    __half* sA = (__half*)smem_raw;
    __half* sM = (__half*)(smem_raw + 9216);
    int2*   sE = (int2*)(smem_raw + 18432);
    __half* sW1 = (__half*)(smem_raw + 18432);
    __half* sW2 = (__half*)(smem_raw + 18432 + 5120);
    float (*sP)[2] = (float(*)[2])(smem_raw + 18432 + 12288);

    int tid = threadIdx.x;
    int wid = tid >> 5;
    int lane = tid & 31;
    int rbase = blockIdx.x * 64;
    int rend = min(rbase + 64, N_NODES);

    if (rbase + 64 > N_NODES) {
        for (int i = tid; i < 64 * 36; i += 256) {
            ((uint32_t*)sA)[i] = 0;
            ((uint32_t*)sM)[i] = 0;
        }
    }
    int ebase = g_off[rbase];
    int etotal = g_off[rend] - ebase;
    bool use_smem = (etotal <= EDGE_CAP2);
    if (use_smem) {
        for (int i = tid; i < etotal; i += 256)
            sE[i] = g_edges[ebase + i];
    }
    __syncthreads();

    const float2* out2 = (const float2*)out;     // ego1 = out[:,64:128]
    const char* base = (const char*)g_egoBh + lane * 4;
    for (int rr = 0; rr < 8; rr += 2) {
        int lrow = wid * 8 + rr;
        int r0 = rbase + lrow;
        if (r0 >= N_NODES) break;
        int r1 = r0 + 1;
        bool v1 = (r1 < N_NODES);
        int s0 = g_off[r0], e0 = g_off[r0 + 1];
        int s1 = v1 ? g_off[r1] : 0, e1 = v1 ? g_off[r1 + 1] : 0;
        float ax0 = 0.f, ay0 = 0.f, ax1 = 0.f, ay1 = 0.f;
        if (use_smem) {
            int rs1 = v1 ? s1 - ebase : 0, re1 = v1 ? e1 - ebase : 0;
            gather_pair(sE, base, s0 - ebase, e0 - ebase, rs1, re1,
                        ax0, ay0, ax1, ay1);
        } else {
            gather_pair(g_edges, base, s0, e0, s1, e1,
                        ax0, ay0, ax1, ay1);
        }
        float2 eg = out2[r0 * 80 + 32 + lane];
        *(__half2*)&sA[lrow * 72 + 2 * lane] = __floats2half2_rn(eg.x + ax0, eg.y + ay0);
        *(__half2*)&sM[lrow * 72 + 2 * lane] = __floats2half2_rn(eg.x * ax0, eg.y * ay0);
        if (v1) {
            float2 eg1 = out2[r1 * 80 + 32 + lane];
            *(__half2*)&sA[(lrow + 1) * 72 + 2 * lane] = __floats2half2_rn(eg1.x + ax1, eg1.y + ay1);
            *(__half2*)&sM[(lrow + 1) * 72 + 2 * lane] = __floats2half2_rn(eg1.x * ax1, eg1.y * ay1);
        }
    }
    __syncthreads();

    for (int i = tid; i < 320; i += 256) {
        ((int4*)sW1)[i] = ((const int4*)g_w1hB)[i];
        ((int4*)sW2)[i] = ((const int4*)g_w2hB)[i];
    }
    __syncthreads();

    int t = wid >> 1;
    int h = wid & 1;

    float d1[8], d2[8];
    #pragma unroll
    for (int nt = 0; nt < 2; nt++) {
        int c = h * 16 + nt * 8 + (lane & 3) * 2;
        float bb1a = b1[c], bb1b = b1[c + 1];
        float bb2a = b2[c], bb2b = b2[c + 1];
        d1[nt * 4 + 0] = bb1a; d1[nt * 4 + 1] = bb1b;
        d1[nt * 4 + 2] = bb1a; d1[nt * 4 + 3] = bb1b;
        d2[nt * 4 + 0] = bb2a; d2[nt * 4 + 1] = bb2b;
        d2[nt * 4 + 2] = bb2a; d2[nt * 4 + 3] = bb2b;
    }

    int q = lane >> 3;
    int ri = lane & 7;
    int arow = t * 16 + (q & 1) * 8 + ri;
    int acol = (q >> 1) * 8;
    uint32_t aA = smem_u32(&sA[arow * 72 + acol]);
    uint32_t aM = smem_u32(&sM[arow * 72 + acol]);
    int g2 = q & 1;
    uint32_t bW1 = smem_u32(&sW1[(g2 * 8 + ri) * 40 + h * 16]);
    uint32_t bW2 = smem_u32(&sW2[(g2 * 8 + ri) * 40 + h * 16]);

    #pragma unroll
    for (int ks = 0; ks < 4; ks++) {
        uint32_t a0, a1, a2, a3;
        LDSM_X4(a0, a1, a2, a3, aA + ks * 32);
        #pragma unroll
        for (int nt = 0; nt < 2; nt++) {
            uint32_t b0, b1r;
            LDSM_X2T(b0, b1r, bW1 + ks * 16 * 80 + nt * 16);
            MMA16816(&d1[nt * 4], a0, a1, a2, a3, b0, b1r);
        }
        LDSM_X4(a0, a1, a2, a3, aM + ks * 32);
        #pragma unroll
        for (int nt = 0; nt < 2; nt++) {
            uint32_t b0, b1r;
            LDSM_X2T(b0, b1r, bW2 + ks * 16 * 80 + nt * 16);
            MMA16816(&d2[nt * 4], a0, a1, a2, a3, b0, b1r);
        }
    }

    float ss0 = 0.f, ss1 = 0.f;
    #pragma unroll
    for (int nt = 0; nt < 2; nt++) {
        #pragma unroll
        for (int i = 0; i < 4; i++) {
            float v1 = d1[nt * 4 + i], v2 = d2[nt * 4 + i];
            float v = (v1 > 0.f ? v1 : 0.01f * v1) + (v2 > 0.f ? v2 : 0.01f * v2);
            d1[nt * 4 + i] = v;
            if (i < 2) ss0 += v * v; else ss1 += v * v;
        }
    }
    ss0 += __shfl_xor_sync(0xFFFFFFFFu, ss0, 1);
    ss0 += __shfl_xor_sync(0xFFFFFFFFu, ss0, 2);
    ss1 += __shfl_xor_sync(0xFFFFFFFFu, ss1, 1);
    ss1 += __shfl_xor_sync(0xFFFFFFFFu, ss1, 2);
    if ((lane & 3) == 0) {
        sP[t * 16 + (lane >> 2)][h] = ss0;
        sP[t * 16 + (lane >> 2) + 8][h] = ss1;
    }
    __syncthreads();

    int r0o = t * 16 + (lane >> 2);
    int r1o = r0o + 8;
    float inv0 = 1.f / fmaxf(sqrtf(sP[r0o][0] + sP[r0o][1]), 1e-12f);
    float inv1 = 1.f / fmaxf(sqrtf(sP[r1o][0] + sP[r1o][1]), 1e-12f);
    int gr0 = rbase + r0o, gr1 = rbase + r1o;
    #pragma unroll
    for (int nt = 0; nt < 2; nt++) {
        int c = h * 16 + nt * 8 + (lane & 3) * 2;
        if (gr0 < N_NODES) {
            *(float2*)&out[gr0 * 160 + 128 + c] =
                make_float2(d1[nt * 4 + 0] * inv0, d1[nt * 4 + 1] * inv0);
        }
        if (gr1 < N_NODES) {
            *(float2*)&out[gr1 * 160 + 128 + c] =
                make_float2(d1[nt * 4 + 2] * inv1, d1[nt * 4 + 3] * inv1);
        }
    }
}

// ---------------------------------------------------------------------------
extern "C" void kernel_launch(void* const* d_in, const int* in_sizes, int n_in,
                              void* d_out, int out_size)
{
    const float* user_tab = (const float*)d_in[0];
    const float* entity_tab = (const float*)d_in[1];
    const float* A_vals = (const float*)d_in[2];
    const float* W1_1 = (const float*)d_in[3];
    const float* b1_1 = (const float*)d_in[4];
    const float* W2_1 = (const float*)d_in[5];
    const float* b2_1 = (const float*)d_in[6];
    const float* W1_2 = (const float*)d_in[7];
    const float* b1_2 = (const float*)d_in[8];
    const float* W2_2 = (const float*)d_in[9];
    const float* b2_2 = (const float*)d_in[10];
    const int* A_rows = (const int*)d_in[11];
    const int* A_cols = (const int*)d_in[12];
    float* out = (float*)d_out;

    int eg = (N_EDGES + 255) / 256;

    void* cnt_ptr = nullptr;
    cudaGetSymbolAddress(&cnt_ptr, g_cnt);
    cudaMemsetAsync(cnt_ptr, 0, N_NODES * sizeof(int));
    void* st_ptr = nullptr;
    cudaGetSymbolAddress(&st_ptr, g_state);
    cudaMemsetAsync(st_ptr, 0, SCAN_NB * sizeof(ull));

    // 0: init (ego0 -> out[:,0:64] + fp16 shadow + histogram + weight pack)
    k_init<<<(N_NODES * 16 + 255) / 256, 256>>>(
        (const float4*)user_tab, (const float4*)entity_tab, A_rows,
        W1_1, W2_1, W1_2, W2_2, (float4*)out);
    // 1: scan
    k_scan<<<SCAN_NB, SCAN_BS>>>();
    // 2: scatter (columns stored as pre-scaled byte offsets)
    k_scatter<<<eg, 256>>>(A_rows, A_cols, A_vals);
    // 3: fused layer 1
    k_layer1<<<(N_NODES + 63) / 64, 256>>>(b1_1, b2_1, out);
    // 4: fused layer 2
    k_layer2<<<(N_NODES + 63) / 64, 256>>>(b1_2, b2_2, out);
}